// round 6
// baseline (speedup 1.0000x reference)
#include <cuda_runtime.h>
#include <cstdint>

// GMM log-likelihood, N=524288, K=32, D=8 — tf32 mma.sync formulation
// (legacy HMMA path; tcgen05 unavailable: harness PTX targets sm_103 non-'a').
//
// wll[n,k] = sum_c F[n][c] * C[k][c], 48 padded features F = [x_i*x_j (i<=j),
// x_i, 1, 0,0,0], coefs from precision matrix P = W^T W, log2 domain, max
// const M folded. fp32 accuracy via 3-term tf32 split over K=144:
//   A blocks [F1 F1 F2] x B blocks [C1 C2 C1]  (missing F2*C2 ~ 2^-22)
// m16n8k8: warp tile = 16 points x 32 comps = 4 n-tiles x 18 k-steps = 72 HMMA.

typedef unsigned int u32;

#define TPB   128
#define GRID  512
#define ITERS 16          // 512*4 warps * 16 tiles * 16 points = 524288
#define TOTAL_WARPS 2048

#define ASTRIDE_F 106     // floats per staged point row (53 float2; 53%16=5 -> <=2-way)
#define ASTRIDE_B (ASTRIDE_F * 4)
#define AWARP_B   (16 * ASTRIDE_B)      // 6784 B per warp
#define SMEM_B_BYTES 20736              // 2592 float2 (B image, fragment order)
#define SMEM_TOTAL (SMEM_B_BYTES + 4 * AWARP_B)   // 47872 < 48K

__device__ uint2 g_B[2592];   // [kk(18)][r(4) stride 36][n(32)] -> (B[kk*8+r][n], B[kk*8+r+4][n])
__device__ float g_M;

// ---------------- helpers ----------------
__device__ __forceinline__ u32 smem_u32(const void* p) {
    u32 a; asm("{ .reg .u64 t; cvta.to.shared.u64 t, %1; cvt.u32.u64 %0, t; }"
               : "=r"(a) : "l"(p)); return a;
}
__device__ __forceinline__ u32 cvt_tf32(float f) {
    u32 r; asm("cvt.rna.tf32.f32 %0, %1;" : "=r"(r) : "f"(f)); return r;
}
__device__ __forceinline__ float ex2f(float x) {
    float r; asm("ex2.approx.f32 %0, %1;" : "=f"(r) : "f"(x)); return r;
}
__device__ __forceinline__ void sts64(u32 addr, u32 a, u32 b) {
    asm volatile("st.shared.v2.u32 [%0], {%1, %2};" :: "r"(addr), "r"(a), "r"(b) : "memory");
}
__device__ __forceinline__ void lds64(u32& a, u32& b, u32 addr) {
    asm volatile("ld.shared.v2.u32 {%0, %1}, [%2];" : "=r"(a), "=r"(b) : "r"(addr));
}
__device__ __forceinline__ void mma_tf32(float& d0, float& d1, float& d2, float& d3,
                                         u32 a0, u32 a1, u32 a2, u32 a3,
                                         u32 b0, u32 b1) {
    asm volatile(
        "mma.sync.aligned.m16n8k8.row.col.f32.tf32.tf32.f32 "
        "{%0,%1,%2,%3}, {%4,%5,%6,%7}, {%8,%9}, {%0,%1,%2,%3};"
        : "+f"(d0), "+f"(d1), "+f"(d2), "+f"(d3)
        : "r"(a0), "r"(a1), "r"(a2), "r"(a3), "r"(b0), "r"(b1));
}

__device__ __forceinline__ int tri(int i, int j) { return i * (i + 1) / 2 + j; }

// feature c of a point (c is compile-time constant under full unroll)
__device__ __forceinline__ float featval(const float xx[8], int c) {
    const int FI_[36] = {0,0,0,0,0,0,0,0, 1,1,1,1,1,1,1, 2,2,2,2,2,2,
                         3,3,3,3,3, 4,4,4,4, 5,5,5, 6,6, 7};
    const int FJ_[36] = {0,1,2,3,4,5,6,7, 1,2,3,4,5,6,7, 2,3,4,5,6,7,
                         3,4,5,6,7, 4,5,6,7, 5,6,7, 6,7, 7};
    if (c >= 45) return 0.0f;
    if (c == 44) return 1.0f;
    if (c >= 36) return xx[c - 36];
    return xx[FI_[c]] * xx[FJ_[c]];
}

// build 3 octets (U0..U0+2) of this point's features into staged A row.
// stored pair layout: float2 at (u*4+rv) = (F[u*8+rv], F[u*8+rv+4]); lo block at +24.
template<int U0>
__device__ __forceinline__ void build3(const float xx[8], u32 arow) {
#pragma unroll
    for (int du = 0; du < 3; du++) {
        const int u = U0 + du;
#pragma unroll
        for (int rv = 0; rv < 4; rv++) {
            float f0 = featval(xx, u * 8 + rv);
            float f1 = featval(xx, u * 8 + rv + 4);
            u32 h0 = cvt_tf32(f0), h1 = cvt_tf32(f1);
            u32 l0 = cvt_tf32(f0 - __uint_as_float(h0));
            u32 l1 = cvt_tf32(f1 - __uint_as_float(h1));
            sts64(arow + (u * 4 + rv) * 8, h0, h1);
            sts64(arow + (24 + u * 4 + rv) * 8, l0, l1);
        }
    }
}

// ---------------- prep: 32 threads, one per component ----------------
__global__ void gmm_prep(const float* __restrict__ pi,
                         const float* __restrict__ means,
                         const float* __restrict__ cv) {
    const int k = threadIdx.x;

    float L[36];
#pragma unroll
    for (int i = 0; i < 8; i++)
#pragma unroll
        for (int j = 0; j <= i; j++)
            L[tri(i, j)] = cv[k * 64 + i * 8 + j];

    float Ld[8];
#pragma unroll
    for (int i = 0; i < 8; i++) Ld[i] = __fdividef(1.0f, L[tri(i, i)]);

    float W[36];  // W = L^{-1} lower tri
#pragma unroll
    for (int c = 0; c < 8; c++) {
        W[tri(c, c)] = Ld[c];
#pragma unroll
        for (int i = c + 1; i < 8; i++) {
            float t = 0.0f;
#pragma unroll
            for (int p = c; p < i; p++) t += L[tri(i, p)] * W[tri(p, c)];
            W[tri(i, c)] = -t * Ld[i];
        }
    }

    float Pm[8][8];  // P = W^T W
#pragma unroll
    for (int i = 0; i < 8; i++)
#pragma unroll
        for (int j = i; j < 8; j++) {
            float s = 0.0f;
#pragma unroll
            for (int m = j; m < 8; m++) s += W[tri(m, i)] * W[tri(m, j)];
            Pm[i][j] = s; Pm[j][i] = s;
        }

    float mu[8], h[8];
#pragma unroll
    for (int j = 0; j < 8; j++) mu[j] = means[k * 8 + j];
    float q0 = 0.0f;
#pragma unroll
    for (int i = 0; i < 8; i++) {
        float t = 0.0f;
#pragma unroll
        for (int j = 0; j < 8; j++) t += Pm[i][j] * mu[j];
        h[i] = t; q0 += mu[i] * t;
    }

    float logdet = 0.0f;
#pragma unroll
    for (int i = 0; i < 8; i++) logdet += __logf(fabsf(L[tri(i, i)]));
    logdet *= 2.0f;

    float pk = pi[k];
    float mx = pk;
#pragma unroll
    for (int o = 16; o; o >>= 1) mx = fmaxf(mx, __shfl_xor_sync(0xffffffffu, mx, o));
    float se = __expf(pk - mx);
#pragma unroll
    for (int o = 16; o; o >>= 1) se += __shfl_xor_sync(0xffffffffu, se, o);
    float lp = pk - mx - __logf(se);

    const float LOG2E = 1.4426950408889634f;
    const float LOG_2PI = 1.8378770664093453f;
    const float s2 = 0.5f * LOG2E;
    float cst2 = (lp - 0.5f * (8.0f * LOG_2PI + logdet)) * LOG2E;

    float M2 = cst2;
#pragma unroll
    for (int o = 16; o; o >>= 1) M2 = fmaxf(M2, __shfl_xor_sync(0xffffffffu, M2, o));

    // coefs in feature order (products i<=j, linear, const, pad)
    float Cc[48];
    int idx = 0;
#pragma unroll
    for (int i = 0; i < 8; i++)
#pragma unroll
        for (int j = i; j < 8; j++)
            Cc[idx++] = (i == j) ? -s2 * Pm[i][i] : -2.0f * s2 * Pm[i][j];
#pragma unroll
    for (int i = 0; i < 8; i++) Cc[36 + i] = 2.0f * s2 * h[i];
    Cc[44] = cst2 - M2 - s2 * q0;
    Cc[45] = 0.0f; Cc[46] = 0.0f; Cc[47] = 0.0f;

    u32 chi[48], clo[48];
#pragma unroll
    for (int c = 0; c < 48; c++) {
        chi[c] = cvt_tf32(Cc[c]);
        clo[c] = cvt_tf32(Cc[c] - __uint_as_float(chi[c]));
    }

    // B image in fragment order: rows K 0-47 = C1, 48-95 = C2, 96-143 = C1
    for (int kk = 0; kk < 18; kk++) {
        for (int r = 0; r < 4; r++) {
            int K0 = kk * 8 + r, K1 = K0 + 4;
            u32 v0 = (K0 < 48) ? chi[K0] : (K0 < 96) ? clo[K0 - 48] : chi[K0 - 96];
            u32 v1 = (K1 < 48) ? chi[K1] : (K1 < 96) ? clo[K1 - 48] : chi[K1 - 96];
            g_B[kk * 144 + r * 36 + k] = make_uint2(v0, v1);
        }
    }
    if (k == 0) g_M = M2 * 0.69314718055994531f;
}

// ---------------- main ----------------
__global__ void __launch_bounds__(TPB)
gmm_main(const float* __restrict__ x, float* __restrict__ out) {
    extern __shared__ __align__(16) char smem[];
    const u32 sb = smem_u32(smem);                 // B image
    const int tid = threadIdx.x;
    const int wid = tid >> 5;
    const int lane = tid & 31;
    const u32 sa = sb + SMEM_B_BYTES + (u32)wid * AWARP_B;

    // copy B image (20736 B)
    {
        const uint4* g4 = reinterpret_cast<const uint4*>(g_B);
        uint4* s4 = reinterpret_cast<uint4*>(smem);
        for (int i = tid; i < 1296; i += TPB) s4[i] = g4[i];
    }
    __syncthreads();
    const float Mc = g_M;

    const int g = lane >> 2;      // mma row group 0..7
    const int r = lane & 3;       // mma thread-in-group 0..3
    const int pl = lane >> 1;     // feature-stage point 0..15
    const int ph = lane & 1;      // feature-stage half

    const int wglob = blockIdx.x * 4 + wid;
    const u32 arow = sa + (u32)pl * ASTRIDE_B;
    const u32 agrow0 = sa + (u32)g * ASTRIDE_B;
    const u32 agrow1 = sa + (u32)(g + 8) * ASTRIDE_B;

#pragma unroll 1
    for (int it = 0; it < ITERS; it++) {
        const int tile = wglob + it * TOTAL_WARPS;
        const int base = tile * 16;

        __syncwarp();
        // ---- stage A: 2 lanes per point, 3 octets each ----
        {
            const float4* px = reinterpret_cast<const float4*>(x + (size_t)(base + pl) * 8);
            float4 x0 = px[0], x1 = px[1];
            float xx[8] = {x0.x, x0.y, x0.z, x0.w, x1.x, x1.y, x1.z, x1.w};
            if (ph == 0) build3<0>(xx, arow);
            else         build3<3>(xx, arow);
        }
        __syncwarp();

        // ---- 72 HMMA ----
        float d[4][4];
#pragma unroll
        for (int nt = 0; nt < 4; nt++)
#pragma unroll
            for (int e = 0; e < 4; e++) d[nt][e] = 0.0f;

#pragma unroll
        for (int u = 0; u < 6; u++) {       // F1 octets, used for C1 and C2
            u32 a0, a2, a1, a3;
            lds64(a0, a2, agrow0 + (u * 4 + r) * 8);
            lds64(a1, a3, agrow1 + (u * 4 + r) * 8);
#pragma unroll
            for (int rep = 0; rep < 2; rep++) {
                const int kk = u + rep * 6;
#pragma unroll
                for (int nt = 0; nt < 4; nt++) {
                    u32 b0, b1;
                    lds64(b0, b1, sb + (u32)(kk * 144 + r * 36 + nt * 8 + g) * 8);
                    mma_tf32(d[nt][0], d[nt][1], d[nt][2], d[nt][3],
                             a0, a1, a2, a3, b0, b1);
                }
            }
        }
#pragma unroll
        for (int u = 0; u < 6; u++) {       // F2 octets vs C1
            u32 a0, a2, a1, a3;
            lds64(a0, a2, agrow0 + (24 + u * 4 + r) * 8);
            lds64(a1, a3, agrow1 + (24 + u * 4 + r) * 8);
            const int kk = 12 + u;
#pragma unroll
            for (int nt = 0; nt < 4; nt++) {
                u32 b0, b1;
                lds64(b0, b1, sb + (u32)(kk * 144 + r * 36 + nt * 8 + g) * 8);
                mma_tf32(d[nt][0], d[nt][1], d[nt][2], d[nt][3],
                         a0, a1, a2, a3, b0, b1);
            }
        }

        // ---- epilogue: 2 points per thread, 8 comps each ----
        float s0 = 0.0f, s1 = 0.0f;
#pragma unroll
        for (int nt = 0; nt < 4; nt++) {
            s0 += ex2f(d[nt][0]) + ex2f(d[nt][1]);
            s1 += ex2f(d[nt][2]) + ex2f(d[nt][3]);
        }
        s0 += __shfl_xor_sync(0xffffffffu, s0, 1);
        s0 += __shfl_xor_sync(0xffffffffu, s0, 2);
        s1 += __shfl_xor_sync(0xffffffffu, s1, 1);
        s1 += __shfl_xor_sync(0xffffffffu, s1, 2);
        if (r == 0) {
            out[base + g]     = Mc + __logf(fmaxf(s0, 1e-37f));
            out[base + 8 + g] = Mc + __logf(fmaxf(s1, 1e-37f));
        }
    }
}

extern "C" void kernel_launch(void* const* d_in, const int* in_sizes, int n_in,
                              void* d_out, int out_size) {
    const float* x     = (const float*)d_in[0];
    const float* pi    = (const float*)d_in[1];
    const float* means = (const float*)d_in[2];
    const float* cv    = (const float*)d_in[3];
    float* out = (float*)d_out;

    gmm_prep<<<1, 32>>>(pi, means, cv);
    gmm_main<<<GRID, TPB, SMEM_TOTAL>>>(x, out);
}

// round 7
// speedup vs baseline: 1.3694x; 1.3694x over previous
#include <cuda_runtime.h>
#include <cstdint>

// GMM log-likelihood, N=524288, K=32, D=8 — tf32 mma.sync, B-in-registers.
//
// wll[n,k] = sum_c F[n][c] * C[k][c], 48 padded features F = [x_i*x_j (i<=j),
// x_i, 1, 0,0,0], coefs from precision matrix P = W^T W, log2 domain, max
// const M folded. fp32 accuracy via 3-term tf32 split over K=144:
//   A blocks [F1 F1 F2] x B blocks [C1 C2 C1]  (missing F2*C2 ~ 2^-22)
// m16n8k8: warp tile = 16 points x 32 comps = 18 k-steps x 4 n-tiles = 72 HMMA.
//
// Round-7: B fragments (12 distinct octets x 4 n-tiles = 96 regs) loaded once
// per thread from global; per-tile smem ops drop 120 -> 48; persistent strided
// grid (456 = 152 SM x 3 CTAs); x prefetch across tiles.

typedef unsigned int u32;

#define TPB    128
#define GRIDN  456
#define TW     (GRIDN * 4)     // total warps = 1824
#define NW     32768           // total warp-tiles (x16 points = 524288)

#define ASTRIDE_B 424          // 53 float2 per staged point (5-pair pad)
#define AWARP_B   (16 * ASTRIDE_B)
#define SMEM_TOTAL (4 * AWARP_B)   // 27136 B (A staging only)

__device__ uint2 g_B[2592];   // [kk(18)][r(4) stride 36][n(32)] -> (B[kk*8+r][n], B[kk*8+r+4][n])
__device__ float g_M;

// ---------------- helpers ----------------
__device__ __forceinline__ u32 smem_u32(const void* p) {
    u32 a; asm("{ .reg .u64 t; cvta.to.shared.u64 t, %1; cvt.u32.u64 %0, t; }"
               : "=r"(a) : "l"(p)); return a;
}
__device__ __forceinline__ u32 cvt_tf32(float f) {
    u32 r; asm("cvt.rna.tf32.f32 %0, %1;" : "=r"(r) : "f"(f)); return r;
}
__device__ __forceinline__ float ex2f(float x) {
    float r; asm("ex2.approx.f32 %0, %1;" : "=f"(r) : "f"(x)); return r;
}
__device__ __forceinline__ void sts64(u32 addr, u32 a, u32 b) {
    asm volatile("st.shared.v2.u32 [%0], {%1, %2};" :: "r"(addr), "r"(a), "r"(b) : "memory");
}
__device__ __forceinline__ void lds64(u32& a, u32& b, u32 addr) {
    asm volatile("ld.shared.v2.u32 {%0, %1}, [%2];" : "=r"(a), "=r"(b) : "r"(addr));
}
__device__ __forceinline__ void mma_tf32(float& d0, float& d1, float& d2, float& d3,
                                         u32 a0, u32 a1, u32 a2, u32 a3,
                                         u32 b0, u32 b1) {
    asm volatile(
        "mma.sync.aligned.m16n8k8.row.col.f32.tf32.tf32.f32 "
        "{%0,%1,%2,%3}, {%4,%5,%6,%7}, {%8,%9}, {%0,%1,%2,%3};"
        : "+f"(d0), "+f"(d1), "+f"(d2), "+f"(d3)
        : "r"(a0), "r"(a1), "r"(a2), "r"(a3), "r"(b0), "r"(b1));
}

__device__ __forceinline__ int tri(int i, int j) { return i * (i + 1) / 2 + j; }

// feature c of a point (c compile-time under full unroll)
__device__ __forceinline__ float featval(const float xx[8], int c) {
    const int FI_[36] = {0,0,0,0,0,0,0,0, 1,1,1,1,1,1,1, 2,2,2,2,2,2,
                         3,3,3,3,3, 4,4,4,4, 5,5,5, 6,6, 7};
    const int FJ_[36] = {0,1,2,3,4,5,6,7, 1,2,3,4,5,6,7, 2,3,4,5,6,7,
                         3,4,5,6,7, 4,5,6,7, 5,6,7, 6,7, 7};
    if (c >= 45) return 0.0f;
    if (c == 44) return 1.0f;
    if (c >= 36) return xx[c - 36];
    return xx[FI_[c]] * xx[FJ_[c]];
}

// build 3 octets (U0..U0+2) of this point's features into its staged A row.
// pair layout: float2 slot (u*4+rv) = (F[u*8+rv], F[u*8+rv+4]); lo block at +24.
template<int U0>
__device__ __forceinline__ void build3(const float xx[8], u32 arow) {
#pragma unroll
    for (int du = 0; du < 3; du++) {
        const int u = U0 + du;
#pragma unroll
        for (int rv = 0; rv < 4; rv++) {
            float f0 = featval(xx, u * 8 + rv);
            float f1 = featval(xx, u * 8 + rv + 4);
            u32 h0 = cvt_tf32(f0), h1 = cvt_tf32(f1);
            u32 l0 = cvt_tf32(f0 - __uint_as_float(h0));
            u32 l1 = cvt_tf32(f1 - __uint_as_float(h1));
            sts64(arow + (u * 4 + rv) * 8, h0, h1);
            sts64(arow + (24 + u * 4 + rv) * 8, l0, l1);
        }
    }
}

// ---------------- prep: 32 threads, one per component ----------------
__global__ void gmm_prep(const float* __restrict__ pi,
                         const float* __restrict__ means,
                         const float* __restrict__ cv) {
    const int k = threadIdx.x;

    float L[36];
#pragma unroll
    for (int i = 0; i < 8; i++)
#pragma unroll
        for (int j = 0; j <= i; j++)
            L[tri(i, j)] = cv[k * 64 + i * 8 + j];

    float Ld[8];
#pragma unroll
    for (int i = 0; i < 8; i++) Ld[i] = __fdividef(1.0f, L[tri(i, i)]);

    float W[36];  // W = L^{-1} lower tri
#pragma unroll
    for (int c = 0; c < 8; c++) {
        W[tri(c, c)] = Ld[c];
#pragma unroll
        for (int i = c + 1; i < 8; i++) {
            float t = 0.0f;
#pragma unroll
            for (int p = c; p < i; p++) t += L[tri(i, p)] * W[tri(p, c)];
            W[tri(i, c)] = -t * Ld[i];
        }
    }

    float Pm[8][8];  // P = W^T W
#pragma unroll
    for (int i = 0; i < 8; i++)
#pragma unroll
        for (int j = i; j < 8; j++) {
            float s = 0.0f;
#pragma unroll
            for (int m = j; m < 8; m++) s += W[tri(m, i)] * W[tri(m, j)];
            Pm[i][j] = s; Pm[j][i] = s;
        }

    float mu[8], h[8];
#pragma unroll
    for (int j = 0; j < 8; j++) mu[j] = means[k * 8 + j];
    float q0 = 0.0f;
#pragma unroll
    for (int i = 0; i < 8; i++) {
        float t = 0.0f;
#pragma unroll
        for (int j = 0; j < 8; j++) t += Pm[i][j] * mu[j];
        h[i] = t; q0 += mu[i] * t;
    }

    float logdet = 0.0f;
#pragma unroll
    for (int i = 0; i < 8; i++) logdet += __logf(fabsf(L[tri(i, i)]));
    logdet *= 2.0f;

    float pk = pi[k];
    float mx = pk;
#pragma unroll
    for (int o = 16; o; o >>= 1) mx = fmaxf(mx, __shfl_xor_sync(0xffffffffu, mx, o));
    float se = __expf(pk - mx);
#pragma unroll
    for (int o = 16; o; o >>= 1) se += __shfl_xor_sync(0xffffffffu, se, o);
    float lp = pk - mx - __logf(se);

    const float LOG2E = 1.4426950408889634f;
    const float LOG_2PI = 1.8378770664093453f;
    const float s2 = 0.5f * LOG2E;
    float cst2 = (lp - 0.5f * (8.0f * LOG_2PI + logdet)) * LOG2E;

    float M2 = cst2;
#pragma unroll
    for (int o = 16; o; o >>= 1) M2 = fmaxf(M2, __shfl_xor_sync(0xffffffffu, M2, o));

    // coefs in feature order (products i<=j, linear, const, pad)
    float Cc[48];
    int idx = 0;
#pragma unroll
    for (int i = 0; i < 8; i++)
#pragma unroll
        for (int j = i; j < 8; j++)
            Cc[idx++] = (i == j) ? -s2 * Pm[i][i] : -2.0f * s2 * Pm[i][j];
#pragma unroll
    for (int i = 0; i < 8; i++) Cc[36 + i] = 2.0f * s2 * h[i];
    Cc[44] = cst2 - M2 - s2 * q0;
    Cc[45] = 0.0f; Cc[46] = 0.0f; Cc[47] = 0.0f;

    u32 chi[48], clo[48];
#pragma unroll
    for (int c = 0; c < 48; c++) {
        chi[c] = cvt_tf32(Cc[c]);
        clo[c] = cvt_tf32(Cc[c] - __uint_as_float(chi[c]));
    }

    // B image in fragment order: K rows 0-47 = C1, 48-95 = C2, 96-143 = C1
    for (int kk = 0; kk < 18; kk++) {
        for (int r = 0; r < 4; r++) {
            int K0 = kk * 8 + r, K1 = K0 + 4;
            u32 v0 = (K0 < 48) ? chi[K0] : (K0 < 96) ? clo[K0 - 48] : chi[K0 - 96];
            u32 v1 = (K1 < 48) ? chi[K1] : (K1 < 96) ? clo[K1 - 48] : chi[K1 - 96];
            g_B[kk * 144 + r * 36 + k] = make_uint2(v0, v1);
        }
    }
    if (k == 0) g_M = M2 * 0.69314718055994531f;
}

// ---------------- main: persistent, B fragments in registers ----------------
__global__ void __launch_bounds__(TPB, 3)
gmm_main(const float* __restrict__ x, float* __restrict__ out) {
    extern __shared__ __align__(16) char smem[];
    const int tid = threadIdx.x;
    const int wid = tid >> 5;
    const int lane = tid & 31;
    const u32 sa = smem_u32(smem) + (u32)wid * AWARP_B;

    const int g = lane >> 2;      // mma row group 0..7
    const int r = lane & 3;       // thread-in-group 0..3
    const int pl = lane >> 1;     // staged point 0..15
    const int ph = lane & 1;      // staging half

    // B fragments -> registers: 12 distinct octets (6 C1 + 6 C2) x 4 n-tiles
    u32 bf[96];
#pragma unroll
    for (int kk2 = 0; kk2 < 12; kk2++)
#pragma unroll
        for (int nt = 0; nt < 4; nt++) {
            uint2 v = g_B[kk2 * 144 + r * 36 + nt * 8 + g];
            bf[(kk2 * 4 + nt) * 2]     = v.x;
            bf[(kk2 * 4 + nt) * 2 + 1] = v.y;
        }
    const float Mc = g_M;

    const u32 arow   = sa + (u32)pl * ASTRIDE_B;
    const u32 agrow0 = sa + (u32)g * ASTRIDE_B + (u32)r * 8;
    const u32 agrow1 = sa + (u32)(g + 8) * ASTRIDE_B + (u32)r * 8;

    const int wglob = blockIdx.x * 4 + wid;

    int tile = wglob;
    float4 v0, v1;
    if (tile < NW) {
        const float4* px = reinterpret_cast<const float4*>(x + (size_t)(tile * 16 + pl) * 8);
        v0 = px[0]; v1 = px[1];
    }

#pragma unroll 1
    while (tile < NW) {
        const int base = tile * 16;
        float xx[8] = {v0.x, v0.y, v0.z, v0.w, v1.x, v1.y, v1.z, v1.w};

        // prefetch next tile's x
        const int tn = tile + TW;
        if (tn < NW) {
            const float4* px = reinterpret_cast<const float4*>(x + (size_t)(tn * 16 + pl) * 8);
            v0 = px[0]; v1 = px[1];
        }

        // ---- stage A fragments (2 lanes per point, 3 octets each) ----
        __syncwarp();
        if (ph == 0) build3<0>(xx, arow);
        else         build3<3>(xx, arow);
        __syncwarp();

        // ---- 72 HMMA, B from registers ----
        float d[4][4];
#pragma unroll
        for (int nt = 0; nt < 4; nt++)
#pragma unroll
            for (int e = 0; e < 4; e++) d[nt][e] = 0.0f;

#pragma unroll
        for (int u = 0; u < 6; u++) {       // F1 octets: vs C1 (bf[u]) and C2 (bf[6+u])
            u32 a0, a2, a1, a3;
            lds64(a0, a2, agrow0 + u * 32);
            lds64(a1, a3, agrow1 + u * 32);
#pragma unroll
            for (int nt = 0; nt < 4; nt++)
                mma_tf32(d[nt][0], d[nt][1], d[nt][2], d[nt][3],
                         a0, a1, a2, a3,
                         bf[(u * 4 + nt) * 2], bf[(u * 4 + nt) * 2 + 1]);
#pragma unroll
            for (int nt = 0; nt < 4; nt++)
                mma_tf32(d[nt][0], d[nt][1], d[nt][2], d[nt][3],
                         a0, a1, a2, a3,
                         bf[((6 + u) * 4 + nt) * 2], bf[((6 + u) * 4 + nt) * 2 + 1]);
        }
#pragma unroll
        for (int u = 0; u < 6; u++) {       // F2 octets vs C1 (bf[u])
            u32 a0, a2, a1, a3;
            lds64(a0, a2, agrow0 + 192 + u * 32);
            lds64(a1, a3, agrow1 + 192 + u * 32);
#pragma unroll
            for (int nt = 0; nt < 4; nt++)
                mma_tf32(d[nt][0], d[nt][1], d[nt][2], d[nt][3],
                         a0, a1, a2, a3,
                         bf[(u * 4 + nt) * 2], bf[(u * 4 + nt) * 2 + 1]);
        }

        // ---- epilogue: thread (g,r) holds comps {nt*8+2r, nt*8+2r+1} of
        //      points g (d0,d1) and g+8 (d2,d3); reduce over r ----
        float s0 = 0.0f, s1 = 0.0f;
#pragma unroll
        for (int nt = 0; nt < 4; nt++) {
            s0 += ex2f(d[nt][0]) + ex2f(d[nt][1]);
            s1 += ex2f(d[nt][2]) + ex2f(d[nt][3]);
        }
        s0 += __shfl_xor_sync(0xffffffffu, s0, 1);
        s0 += __shfl_xor_sync(0xffffffffu, s0, 2);
        s1 += __shfl_xor_sync(0xffffffffu, s1, 1);
        s1 += __shfl_xor_sync(0xffffffffu, s1, 2);
        if (r == 0) {
            out[base + g]     = Mc + __logf(fmaxf(s0, 1e-37f));
            out[base + 8 + g] = Mc + __logf(fmaxf(s1, 1e-37f));
        }

        tile = tn;
    }
}

extern "C" void kernel_launch(void* const* d_in, const int* in_sizes, int n_in,
                              void* d_out, int out_size) {
    const float* x     = (const float*)d_in[0];
    const float* pi    = (const float*)d_in[1];
    const float* means = (const float*)d_in[2];
    const float* cv    = (const float*)d_in[3];
    float* out = (float*)d_out;

    gmm_prep<<<1, 32>>>(pi, means, cv);
    gmm_main<<<GRIDN, TPB, SMEM_TOTAL>>>(x, out);
}

// round 8
// speedup vs baseline: 1.5207x; 1.1105x over previous
#include <cuda_runtime.h>
#include <cstdint>

// GMM log-likelihood, N=524288, K=32, D=8 — tf32 mma.sync, round 8.
//
// wll[n,k] = sum_c F[n][c]*C[k][c]; 48 padded features F = [x_i*x_j (i<=j),
// x_i, 1, pad]; coefs from precision matrix P = W^T W; log2 domain, max
// const folded. fp32 accuracy via split products over K=144:
//   A blocks [F1 F1 F2] x B blocks [C1 C2 C1]
// Split by BIT TRUNCATION (hi = f & 0xFFFFE000, lo = f - hi fed raw):
// tf32 HMMA reads only the top 19 register bits, so no cvt instructions
// are needed; residual error ~2^-20 per term, ~500x under tolerance.
//
// A staging: per point 24 16-byte chunks (hi_k, hi_k+4, lo_k, lo_k+4),
// point stride 432 B (odd 16B-stride => perfect 4-phase STS.128/LDS.128).
// Per warp-tile: 12 STS.128 + 12 LDS.128 + 72 HMMA. B in registers (96).

typedef unsigned int u32;

#define TPB    128
#define GRIDN  456
#define TW     (GRIDN * 4)     // 1824 warps
#define NW     32768           // warp-tiles (x16 points = 524288)

#define PSTRIDE_B 432          // bytes per staged point (27 x 16B chunks, 24 used)
#define AWARP_B   (16 * PSTRIDE_B)          // 6912 B
#define SMEM_TOTAL (4 * AWARP_B)            // 27648 B

__device__ uint2 g_B[2592];   // [kk(18)][r(4) stride 36][n(32)]
__device__ float g_M;

// ---------------- helpers ----------------
__device__ __forceinline__ u32 smem_u32(const void* p) {
    u32 a; asm("{ .reg .u64 t; cvta.to.shared.u64 t, %1; cvt.u32.u64 %0, t; }"
               : "=r"(a) : "l"(p)); return a;
}
__device__ __forceinline__ u32 cvt_tf32(float f) {
    u32 r; asm("cvt.rna.tf32.f32 %0, %1;" : "=r"(r) : "f"(f)); return r;
}
__device__ __forceinline__ float ex2f(float x) {
    float r; asm("ex2.approx.f32 %0, %1;" : "=f"(r) : "f"(x)); return r;
}
__device__ __forceinline__ void sts128(u32 addr, u32 a, u32 b, u32 c, u32 d) {
    asm volatile("st.shared.v4.b32 [%0], {%1, %2, %3, %4};"
                 :: "r"(addr), "r"(a), "r"(b), "r"(c), "r"(d) : "memory");
}
__device__ __forceinline__ void lds128(u32& a, u32& b, u32& c, u32& d, u32 addr) {
    asm volatile("ld.shared.v4.b32 {%0, %1, %2, %3}, [%4];"
                 : "=r"(a), "=r"(b), "=r"(c), "=r"(d) : "r"(addr));
}
__device__ __forceinline__ void mma_tf32(float& d0, float& d1, float& d2, float& d3,
                                         u32 a0, u32 a1, u32 a2, u32 a3,
                                         u32 b0, u32 b1) {
    asm volatile(
        "mma.sync.aligned.m16n8k8.row.col.f32.tf32.tf32.f32 "
        "{%0,%1,%2,%3}, {%4,%5,%6,%7}, {%8,%9}, {%0,%1,%2,%3};"
        : "+f"(d0), "+f"(d1), "+f"(d2), "+f"(d3)
        : "r"(a0), "r"(a1), "r"(a2), "r"(a3), "r"(b0), "r"(b1));
}

__device__ __forceinline__ int tri(int i, int j) { return i * (i + 1) / 2 + j; }

// feature c of a point (c compile-time under full unroll)
__device__ __forceinline__ float featval(const float xx[8], int c) {
    const int FI_[36] = {0,0,0,0,0,0,0,0, 1,1,1,1,1,1,1, 2,2,2,2,2,2,
                         3,3,3,3,3, 4,4,4,4, 5,5,5, 6,6, 7};
    const int FJ_[36] = {0,1,2,3,4,5,6,7, 1,2,3,4,5,6,7, 2,3,4,5,6,7,
                         3,4,5,6,7, 4,5,6,7, 5,6,7, 6,7, 7};
    if (c >= 45) return 0.0f;
    if (c == 44) return 1.0f;
    if (c >= 36) return xx[c - 36];
    return xx[FI_[c]] * xx[FJ_[c]];
}

// stage chunks PH*12 .. PH*12+11 of this point (truncation split, no cvt)
template<int PH>
__device__ __forceinline__ void stage12(const float xx[8], u32 arow) {
#pragma unroll
    for (int s = 0; s < 12; s++) {
        const int c  = PH * 12 + s;      // chunk 0..23
        const int u  = c >> 2;
        const int rv = c & 3;
        float f0 = featval(xx, u * 8 + rv);
        float f1 = featval(xx, u * 8 + rv + 4);
        u32 h0 = __float_as_uint(f0) & 0xFFFFE000u;
        u32 h1 = __float_as_uint(f1) & 0xFFFFE000u;
        u32 l0 = __float_as_uint(f0 - __uint_as_float(h0));
        u32 l1 = __float_as_uint(f1 - __uint_as_float(h1));
        sts128(arow + c * 16, h0, h1, l0, l1);
    }
}

// ---------------- prep: 32 threads, one per component ----------------
__global__ void gmm_prep(const float* __restrict__ pi,
                         const float* __restrict__ means,
                         const float* __restrict__ cv) {
    const int k = threadIdx.x;

    float L[36];
#pragma unroll
    for (int i = 0; i < 8; i++)
#pragma unroll
        for (int j = 0; j <= i; j++)
            L[tri(i, j)] = cv[k * 64 + i * 8 + j];

    float Ld[8];
#pragma unroll
    for (int i = 0; i < 8; i++) Ld[i] = __fdividef(1.0f, L[tri(i, i)]);

    float W[36];  // W = L^{-1} lower tri
#pragma unroll
    for (int c = 0; c < 8; c++) {
        W[tri(c, c)] = Ld[c];
#pragma unroll
        for (int i = c + 1; i < 8; i++) {
            float t = 0.0f;
#pragma unroll
            for (int p = c; p < i; p++) t += L[tri(i, p)] * W[tri(p, c)];
            W[tri(i, c)] = -t * Ld[i];
        }
    }

    float Pm[8][8];  // P = W^T W
#pragma unroll
    for (int i = 0; i < 8; i++)
#pragma unroll
        for (int j = i; j < 8; j++) {
            float s = 0.0f;
#pragma unroll
            for (int m = j; m < 8; m++) s += W[tri(m, i)] * W[tri(m, j)];
            Pm[i][j] = s; Pm[j][i] = s;
        }

    float mu[8], h[8];
#pragma unroll
    for (int j = 0; j < 8; j++) mu[j] = means[k * 8 + j];
    float q0 = 0.0f;
#pragma unroll
    for (int i = 0; i < 8; i++) {
        float t = 0.0f;
#pragma unroll
        for (int j = 0; j < 8; j++) t += Pm[i][j] * mu[j];
        h[i] = t; q0 += mu[i] * t;
    }

    float logdet = 0.0f;
#pragma unroll
    for (int i = 0; i < 8; i++) logdet += __logf(fabsf(L[tri(i, i)]));
    logdet *= 2.0f;

    float pk = pi[k];
    float mx = pk;
#pragma unroll
    for (int o = 16; o; o >>= 1) mx = fmaxf(mx, __shfl_xor_sync(0xffffffffu, mx, o));
    float se = __expf(pk - mx);
#pragma unroll
    for (int o = 16; o; o >>= 1) se += __shfl_xor_sync(0xffffffffu, se, o);
    float lp = pk - mx - __logf(se);

    const float LOG2E = 1.4426950408889634f;
    const float LOG_2PI = 1.8378770664093453f;
    const float s2 = 0.5f * LOG2E;
    float cst2 = (lp - 0.5f * (8.0f * LOG_2PI + logdet)) * LOG2E;

    float M2 = cst2;
#pragma unroll
    for (int o = 16; o; o >>= 1) M2 = fmaxf(M2, __shfl_xor_sync(0xffffffffu, M2, o));

    float Cc[48];
    int idx = 0;
#pragma unroll
    for (int i = 0; i < 8; i++)
#pragma unroll
        for (int j = i; j < 8; j++)
            Cc[idx++] = (i == j) ? -s2 * Pm[i][i] : -2.0f * s2 * Pm[i][j];
#pragma unroll
    for (int i = 0; i < 8; i++) Cc[36 + i] = 2.0f * s2 * h[i];
    Cc[44] = cst2 - M2 - s2 * q0;
    Cc[45] = 0.0f; Cc[46] = 0.0f; Cc[47] = 0.0f;

    u32 chi[48], clo[48];
#pragma unroll
    for (int c = 0; c < 48; c++) {
        chi[c] = cvt_tf32(Cc[c]);
        clo[c] = cvt_tf32(Cc[c] - __uint_as_float(chi[c]));
    }

    // B image fragment order: K rows 0-47 = C1, 48-95 = C2, 96-143 = C1
    for (int kk = 0; kk < 18; kk++) {
        for (int r = 0; r < 4; r++) {
            int K0 = kk * 8 + r, K1 = K0 + 4;
            u32 v0 = (K0 < 48) ? chi[K0] : (K0 < 96) ? clo[K0 - 48] : chi[K0 - 96];
            u32 v1 = (K1 < 48) ? chi[K1] : (K1 < 96) ? clo[K1 - 48] : chi[K1 - 96];
            g_B[kk * 144 + r * 36 + k] = make_uint2(v0, v1);
        }
    }
    if (k == 0) g_M = M2 * 0.69314718055994531f;
}

// ---------------- main: persistent, B in registers ----------------
__global__ void __launch_bounds__(TPB, 3)
gmm_main(const float* __restrict__ x, float* __restrict__ out) {
    extern __shared__ __align__(16) char smem[];
    const int tid = threadIdx.x;
    const int wid = tid >> 5;
    const int lane = tid & 31;
    const u32 sa = smem_u32(smem) + (u32)wid * AWARP_B;

    const int g = lane >> 2;      // mma row group 0..7
    const int r = lane & 3;       // thread-in-group 0..3
    const int pl = lane >> 1;     // staged point 0..15
    const int ph = lane & 1;      // staging half

    // B fragments: 12 distinct octets (6 C1 + 6 C2) x 4 n-tiles
    u32 bf[96];
#pragma unroll
    for (int kk2 = 0; kk2 < 12; kk2++)
#pragma unroll
        for (int nt = 0; nt < 4; nt++) {
            uint2 v = g_B[kk2 * 144 + r * 36 + nt * 8 + g];
            bf[(kk2 * 4 + nt) * 2]     = v.x;
            bf[(kk2 * 4 + nt) * 2 + 1] = v.y;
        }
    const float Mc = g_M;

    const u32 arow   = sa + (u32)pl * PSTRIDE_B;
    const u32 agrow0 = sa + (u32)g * PSTRIDE_B + (u32)r * 16;
    const u32 agrow1 = agrow0 + 8 * PSTRIDE_B;

    const int wglob = blockIdx.x * 4 + wid;

    int tile = wglob;
    float4 v0, v1;
    if (tile < NW) {
        const float4* px = reinterpret_cast<const float4*>(x + (size_t)(tile * 16 + pl) * 8);
        v0 = px[0]; v1 = px[1];
    }

#pragma unroll 1
    while (tile < NW) {
        const int base = tile * 16;
        float xx[8] = {v0.x, v0.y, v0.z, v0.w, v1.x, v1.y, v1.z, v1.w};

        // prefetch next tile's x
        const int tn = tile + TW;
        if (tn < NW) {
            const float4* px = reinterpret_cast<const float4*>(x + (size_t)(tn * 16 + pl) * 8);
            v0 = px[0]; v1 = px[1];
        }

        // ---- stage A chunks (2 lanes per point, 12 chunks each) ----
        __syncwarp();
        if (ph == 0) stage12<0>(xx, arow);
        else         stage12<1>(xx, arow);
        __syncwarp();

        // ---- 72 HMMA: per u, 2 LDS.128 then 12 mma ----
        float d[4][4];
#pragma unroll
        for (int nt = 0; nt < 4; nt++)
#pragma unroll
            for (int e = 0; e < 4; e++) d[nt][e] = 0.0f;

#pragma unroll
        for (int u = 0; u < 6; u++) {
            u32 h0, h2, l0, l2, h1, h3, l1, l3;
            lds128(h0, h2, l0, l2, agrow0 + u * 64);
            lds128(h1, h3, l1, l3, agrow1 + u * 64);
#pragma unroll
            for (int nt = 0; nt < 4; nt++)      // F1 x C1
                mma_tf32(d[nt][0], d[nt][1], d[nt][2], d[nt][3],
                         h0, h1, h2, h3,
                         bf[(u * 4 + nt) * 2], bf[(u * 4 + nt) * 2 + 1]);
#pragma unroll
            for (int nt = 0; nt < 4; nt++)      // F1 x C2
                mma_tf32(d[nt][0], d[nt][1], d[nt][2], d[nt][3],
                         h0, h1, h2, h3,
                         bf[((6 + u) * 4 + nt) * 2], bf[((6 + u) * 4 + nt) * 2 + 1]);
#pragma unroll
            for (int nt = 0; nt < 4; nt++)      // F2 x C1
                mma_tf32(d[nt][0], d[nt][1], d[nt][2], d[nt][3],
                         l0, l1, l2, l3,
                         bf[(u * 4 + nt) * 2], bf[(u * 4 + nt) * 2 + 1]);
        }

        // ---- epilogue: thread (g,r) holds points g, g+8; reduce over r ----
        float s0 = 0.0f, s1 = 0.0f;
#pragma unroll
        for (int nt = 0; nt < 4; nt++) {
            s0 += ex2f(d[nt][0]) + ex2f(d[nt][1]);
            s1 += ex2f(d[nt][2]) + ex2f(d[nt][3]);
        }
        s0 += __shfl_xor_sync(0xffffffffu, s0, 1);
        s0 += __shfl_xor_sync(0xffffffffu, s0, 2);
        s1 += __shfl_xor_sync(0xffffffffu, s1, 1);
        s1 += __shfl_xor_sync(0xffffffffu, s1, 2);
        if (r == 0) {
            out[base + g]     = Mc + __logf(fmaxf(s0, 1e-37f));
            out[base + 8 + g] = Mc + __logf(fmaxf(s1, 1e-37f));
        }

        tile = tn;
    }
}

extern "C" void kernel_launch(void* const* d_in, const int* in_sizes, int n_in,
                              void* d_out, int out_size) {
    const float* x     = (const float*)d_in[0];
    const float* pi    = (const float*)d_in[1];
    const float* means = (const float*)d_in[2];
    const float* cv    = (const float*)d_in[3];
    float* out = (float*)d_out;

    gmm_prep<<<1, 32>>>(pi, means, cv);
    gmm_main<<<GRIDN, TPB, SMEM_TOTAL>>>(x, out);
}

// round 9
// speedup vs baseline: 1.5257x; 1.0033x over previous
#include <cuda_runtime.h>
#include <cstdint>

// GMM log-likelihood, N=524288, K=32, D=8 — tf32 mma.sync, round 9:
// software-pipelined (double-buffered A staging).
//
// wll[n,k] = sum_c F[n][c]*C[k][c]; 48 padded features F = [x_i*x_j (i<=j),
// x_i, 1, pad]; coefs from precision matrix P = W^T W; log2 domain, max
// const folded. fp32 accuracy via split products over K=144:
//   A blocks [F1 F1 F2] x B blocks [C1 C2 C1]
// (truncation split: hi = f & 0xFFFFE000, lo = f - hi fed raw; tf32 HMMA
//  reads top 19 register bits; residual ~2^-20 per term).
//
// Pipeline: while the MMA loop for tile t reads staging buffer p, the
// features/split/STS for tile t+1 write buffer p^1 (different pipes), and
// x for tile t+2 is in flight. Per-warp private buffers + in-order LSU +
// one __syncwarp per iteration. B fragments (96 regs) loaded once.

typedef unsigned int u32;

#define TPB    128
#define GRIDN  456
#define TW     (GRIDN * 4)     // 1824 warps
#define NW     32768           // warp-tiles (x16 points)

#define PSTRIDE_B 432          // bytes per staged point (27 x 16B chunks, 24 used)
#define ABUF_B    (16 * PSTRIDE_B)          // 6912 B per buffer
#define AWARP_B   (2 * ABUF_B)              // double buffer
#define SMEM_TOTAL (4 * AWARP_B)            // 55296 B

__device__ uint2 g_B[2592];   // [kk(18)][r(4) stride 36][n(32)]
__device__ float g_M;

// ---------------- helpers ----------------
__device__ __forceinline__ u32 smem_u32(const void* p) {
    u32 a; asm("{ .reg .u64 t; cvta.to.shared.u64 t, %1; cvt.u32.u64 %0, t; }"
               : "=r"(a) : "l"(p)); return a;
}
__device__ __forceinline__ u32 cvt_tf32(float f) {
    u32 r; asm("cvt.rna.tf32.f32 %0, %1;" : "=r"(r) : "f"(f)); return r;
}
__device__ __forceinline__ float ex2f(float x) {
    float r; asm("ex2.approx.f32 %0, %1;" : "=f"(r) : "f"(x)); return r;
}
__device__ __forceinline__ void sts128(u32 addr, u32 a, u32 b, u32 c, u32 d) {
    asm volatile("st.shared.v4.b32 [%0], {%1, %2, %3, %4};"
                 :: "r"(addr), "r"(a), "r"(b), "r"(c), "r"(d) : "memory");
}
__device__ __forceinline__ void lds128(u32& a, u32& b, u32& c, u32& d, u32 addr) {
    asm volatile("ld.shared.v4.b32 {%0, %1, %2, %3}, [%4];"
                 : "=r"(a), "=r"(b), "=r"(c), "=r"(d) : "r"(addr));
}
__device__ __forceinline__ void mma_tf32(float& d0, float& d1, float& d2, float& d3,
                                         u32 a0, u32 a1, u32 a2, u32 a3,
                                         u32 b0, u32 b1) {
    asm volatile(
        "mma.sync.aligned.m16n8k8.row.col.f32.tf32.tf32.f32 "
        "{%0,%1,%2,%3}, {%4,%5,%6,%7}, {%8,%9}, {%0,%1,%2,%3};"
        : "+f"(d0), "+f"(d1), "+f"(d2), "+f"(d3)
        : "r"(a0), "r"(a1), "r"(a2), "r"(a3), "r"(b0), "r"(b1));
}

__device__ __forceinline__ int tri(int i, int j) { return i * (i + 1) / 2 + j; }

__device__ __forceinline__ float featval(const float xx[8], int c) {
    const int FI_[36] = {0,0,0,0,0,0,0,0, 1,1,1,1,1,1,1, 2,2,2,2,2,2,
                         3,3,3,3,3, 4,4,4,4, 5,5,5, 6,6, 7};
    const int FJ_[36] = {0,1,2,3,4,5,6,7, 1,2,3,4,5,6,7, 2,3,4,5,6,7,
                         3,4,5,6,7, 4,5,6,7, 5,6,7, 6,7, 7};
    if (c >= 45) return 0.0f;
    if (c == 44) return 1.0f;
    if (c >= 36) return xx[c - 36];
    return xx[FI_[c]] * xx[FJ_[c]];
}

// stage chunks PH*12 .. PH*12+11 of this point (truncation split)
template<int PH>
__device__ __forceinline__ void stage12(const float xx[8], u32 arow) {
#pragma unroll
    for (int s = 0; s < 12; s++) {
        const int c  = PH * 12 + s;
        const int u  = c >> 2;
        const int rv = c & 3;
        float f0 = featval(xx, u * 8 + rv);
        float f1 = featval(xx, u * 8 + rv + 4);
        u32 h0 = __float_as_uint(f0) & 0xFFFFE000u;
        u32 h1 = __float_as_uint(f1) & 0xFFFFE000u;
        u32 l0 = __float_as_uint(f0 - __uint_as_float(h0));
        u32 l1 = __float_as_uint(f1 - __uint_as_float(h1));
        sts128(arow + c * 16, h0, h1, l0, l1);
    }
}

// ---------------- prep: 32 threads, one per component ----------------
__global__ void gmm_prep(const float* __restrict__ pi,
                         const float* __restrict__ means,
                         const float* __restrict__ cv) {
    const int k = threadIdx.x;

    float L[36];
#pragma unroll
    for (int i = 0; i < 8; i++)
#pragma unroll
        for (int j = 0; j <= i; j++)
            L[tri(i, j)] = cv[k * 64 + i * 8 + j];

    float Ld[8];
#pragma unroll
    for (int i = 0; i < 8; i++) Ld[i] = __fdividef(1.0f, L[tri(i, i)]);

    float W[36];
#pragma unroll
    for (int c = 0; c < 8; c++) {
        W[tri(c, c)] = Ld[c];
#pragma unroll
        for (int i = c + 1; i < 8; i++) {
            float t = 0.0f;
#pragma unroll
            for (int p = c; p < i; p++) t += L[tri(i, p)] * W[tri(p, c)];
            W[tri(i, c)] = -t * Ld[i];
        }
    }

    float Pm[8][8];
#pragma unroll
    for (int i = 0; i < 8; i++)
#pragma unroll
        for (int j = i; j < 8; j++) {
            float s = 0.0f;
#pragma unroll
            for (int m = j; m < 8; m++) s += W[tri(m, i)] * W[tri(m, j)];
            Pm[i][j] = s; Pm[j][i] = s;
        }

    float mu[8], h[8];
#pragma unroll
    for (int j = 0; j < 8; j++) mu[j] = means[k * 8 + j];
    float q0 = 0.0f;
#pragma unroll
    for (int i = 0; i < 8; i++) {
        float t = 0.0f;
#pragma unroll
        for (int j = 0; j < 8; j++) t += Pm[i][j] * mu[j];
        h[i] = t; q0 += mu[i] * t;
    }

    float logdet = 0.0f;
#pragma unroll
    for (int i = 0; i < 8; i++) logdet += __logf(fabsf(L[tri(i, i)]));
    logdet *= 2.0f;

    float pk = pi[k];
    float mx = pk;
#pragma unroll
    for (int o = 16; o; o >>= 1) mx = fmaxf(mx, __shfl_xor_sync(0xffffffffu, mx, o));
    float se = __expf(pk - mx);
#pragma unroll
    for (int o = 16; o; o >>= 1) se += __shfl_xor_sync(0xffffffffu, se, o);
    float lp = pk - mx - __logf(se);

    const float LOG2E = 1.4426950408889634f;
    const float LOG_2PI = 1.8378770664093453f;
    const float s2 = 0.5f * LOG2E;
    float cst2 = (lp - 0.5f * (8.0f * LOG_2PI + logdet)) * LOG2E;

    float M2 = cst2;
#pragma unroll
    for (int o = 16; o; o >>= 1) M2 = fmaxf(M2, __shfl_xor_sync(0xffffffffu, M2, o));

    float Cc[48];
    int idx = 0;
#pragma unroll
    for (int i = 0; i < 8; i++)
#pragma unroll
        for (int j = i; j < 8; j++)
            Cc[idx++] = (i == j) ? -s2 * Pm[i][i] : -2.0f * s2 * Pm[i][j];
#pragma unroll
    for (int i = 0; i < 8; i++) Cc[36 + i] = 2.0f * s2 * h[i];
    Cc[44] = cst2 - M2 - s2 * q0;
    Cc[45] = 0.0f; Cc[46] = 0.0f; Cc[47] = 0.0f;

    u32 chi[48], clo[48];
#pragma unroll
    for (int c = 0; c < 48; c++) {
        chi[c] = cvt_tf32(Cc[c]);
        clo[c] = cvt_tf32(Cc[c] - __uint_as_float(chi[c]));
    }

    // B image fragment order: K rows 0-47 = C1, 48-95 = C2, 96-143 = C1
    for (int kk = 0; kk < 18; kk++) {
        for (int r = 0; r < 4; r++) {
            int K0 = kk * 8 + r, K1 = K0 + 4;
            u32 v0 = (K0 < 48) ? chi[K0] : (K0 < 96) ? clo[K0 - 48] : chi[K0 - 96];
            u32 v1 = (K1 < 48) ? chi[K1] : (K1 < 96) ? clo[K1 - 48] : chi[K1 - 96];
            g_B[kk * 144 + r * 36 + k] = make_uint2(v0, v1);
        }
    }
    if (k == 0) g_M = M2 * 0.69314718055994531f;
}

// ---------------- main: persistent, pipelined, B in registers ----------------
__global__ void __launch_bounds__(TPB, 3)
gmm_main(const float* __restrict__ x, float* __restrict__ out) {
    extern __shared__ __align__(16) char smem[];
    const int tid = threadIdx.x;
    const int wid = tid >> 5;
    const int lane = tid & 31;
    const u32 sa = smem_u32(smem) + (u32)wid * AWARP_B;

    const int g = lane >> 2;      // mma row group 0..7
    const int r = lane & 3;       // thread-in-group 0..3
    const int pl = lane >> 1;     // staged point 0..15
    const int ph = lane & 1;      // staging half

    // B fragments: 12 distinct octets (6 C1 + 6 C2) x 4 n-tiles
    u32 bf[96];
#pragma unroll
    for (int kk2 = 0; kk2 < 12; kk2++)
#pragma unroll
        for (int nt = 0; nt < 4; nt++) {
            uint2 v = g_B[kk2 * 144 + r * 36 + nt * 8 + g];
            bf[(kk2 * 4 + nt) * 2]     = v.x;
            bf[(kk2 * 4 + nt) * 2 + 1] = v.y;
        }
    const float Mc = g_M;

    const u32 arow_base   = sa + (u32)pl * PSTRIDE_B;
    const u32 agrow0_base = sa + (u32)g * PSTRIDE_B + (u32)r * 16;

    const int wglob = blockIdx.x * 4 + wid;

    // ---- prologue: stage tile0 into buf0; prefetch x(tile1) ----
    int tile = wglob;
    if (tile < NW) {
        const float4* px = reinterpret_cast<const float4*>(x + (size_t)(tile * 16 + pl) * 8);
        float4 a0 = px[0], a1 = px[1];
        float xx[8] = {a0.x, a0.y, a0.z, a0.w, a1.x, a1.y, a1.z, a1.w};
        if (ph == 0) stage12<0>(xx, arow_base);
        else         stage12<1>(xx, arow_base);
    }
    float4 v0, v1;
    {
        const int tn = tile + TW;
        if (tn < NW) {
            const float4* px = reinterpret_cast<const float4*>(x + (size_t)(tn * 16 + pl) * 8);
            v0 = px[0]; v1 = px[1];
        }
    }
    __syncwarp();

    u32 p = 0;
#pragma unroll 1
    while (tile < NW) {
        const int base = tile * 16;
        const int tn  = tile + TW;
        const int tn2 = tile + 2 * TW;

        // ---- stage tile t+1 into the other buffer (overlaps MMA of t) ----
        if (tn < NW) {
            float xx[8] = {v0.x, v0.y, v0.z, v0.w, v1.x, v1.y, v1.z, v1.w};
            const u32 arow = arow_base + (p ^ 1) * ABUF_B;
            if (ph == 0) stage12<0>(xx, arow);
            else         stage12<1>(xx, arow);
        }
        // ---- prefetch x for tile t+2 ----
        if (tn2 < NW) {
            const float4* px = reinterpret_cast<const float4*>(x + (size_t)(tn2 * 16 + pl) * 8);
            v0 = px[0]; v1 = px[1];
        }

        // ---- 72 HMMA for tile t from buffer p ----
        const u32 agrow0 = agrow0_base + p * ABUF_B;
        const u32 agrow1 = agrow0 + 8 * PSTRIDE_B;

        float d[4][4];
#pragma unroll
        for (int nt = 0; nt < 4; nt++)
#pragma unroll
            for (int e = 0; e < 4; e++) d[nt][e] = 0.0f;

#pragma unroll
        for (int u = 0; u < 6; u++) {
            u32 h0, h2, l0, l2, h1, h3, l1, l3;
            lds128(h0, h2, l0, l2, agrow0 + u * 64);
            lds128(h1, h3, l1, l3, agrow1 + u * 64);
#pragma unroll
            for (int nt = 0; nt < 4; nt++)      // F1 x C1
                mma_tf32(d[nt][0], d[nt][1], d[nt][2], d[nt][3],
                         h0, h1, h2, h3,
                         bf[(u * 4 + nt) * 2], bf[(u * 4 + nt) * 2 + 1]);
#pragma unroll
            for (int nt = 0; nt < 4; nt++)      // F1 x C2
                mma_tf32(d[nt][0], d[nt][1], d[nt][2], d[nt][3],
                         h0, h1, h2, h3,
                         bf[((6 + u) * 4 + nt) * 2], bf[((6 + u) * 4 + nt) * 2 + 1]);
#pragma unroll
            for (int nt = 0; nt < 4; nt++)      // F2 x C1
                mma_tf32(d[nt][0], d[nt][1], d[nt][2], d[nt][3],
                         l0, l1, l2, l3,
                         bf[(u * 4 + nt) * 2], bf[(u * 4 + nt) * 2 + 1]);
        }

        // ---- epilogue: thread (g,r) holds points g, g+8; reduce over r ----
        float s0 = 0.0f, s1 = 0.0f;
#pragma unroll
        for (int nt = 0; nt < 4; nt++) {
            s0 += ex2f(d[nt][0]) + ex2f(d[nt][1]);
            s1 += ex2f(d[nt][2]) + ex2f(d[nt][3]);
        }
        s0 += __shfl_xor_sync(0xffffffffu, s0, 1);
        s0 += __shfl_xor_sync(0xffffffffu, s0, 2);
        s1 += __shfl_xor_sync(0xffffffffu, s1, 1);
        s1 += __shfl_xor_sync(0xffffffffu, s1, 2);
        if (r == 0) {
            out[base + g]     = Mc + __logf(fmaxf(s0, 1e-37f));
            out[base + 8 + g] = Mc + __logf(fmaxf(s1, 1e-37f));
        }

        __syncwarp();
        tile = tn;
        p ^= 1;
    }
}

extern "C" void kernel_launch(void* const* d_in, const int* in_sizes, int n_in,
                              void* d_out, int out_size) {
    const float* x     = (const float*)d_in[0];
    const float* pi    = (const float*)d_in[1];
    const float* means = (const float*)d_in[2];
    const float* cv    = (const float*)d_in[3];
    float* out = (float*)d_out;

    gmm_prep<<<1, 32>>>(pi, means, cv);
    cudaFuncSetAttribute(gmm_main, cudaFuncAttributeMaxDynamicSharedMemorySize, SMEM_TOTAL);
    gmm_main<<<GRIDN, TPB, SMEM_TOTAL>>>(x, out);
}

// round 10
// speedup vs baseline: 1.5932x; 1.0443x over previous
#include <cuda_runtime.h>
#include <cuda_bf16.h>
#include <cstdint>

// GMM log-likelihood, N=524288, K=32, D=8 — bf16 mma.sync m16n8k16, round 10.
//
// wll[n,k] = sum_c F[n][c]*C[k][c]; 48 padded features F = [x_i*x_j (i<=j),
// x_i, 1, pad]; coefs from precision matrix P = W^T W; log2 domain, max
// const folded. Accuracy via 4-term bf16 block product over K=192:
//   A = [F1 F1 F2 F2], B = [C1 C2 C1 C2]  ->  (F1+F2)(C1+C2) ~ F*C (2^-16)
// F1 = bf16-truncation of F (PRMT byte pack, no cvt), F2 = trunc(F - F1);
// C1 = bf16-rn(C), C2 = bf16-rn(C - C1) (prep-side).
//
// Per warp-tile (16 points x 32 comps): 12 STS.128 + 12 LDS.128 + 48 HMMA.
// B fragments: 6 distinct k16-steps x 4 n-tiles x 2 regs = 48 regs.
// Low regs -> 4+ CTAs/SM (the tf32 version was register-file bound at 3).

typedef unsigned int u32;
typedef unsigned short u16;

#define TPB    128
#define GRIDN  608             // 152 SMs x 4 CTAs
#define TW     (GRIDN * 4)     // 2432 warps
#define NW     32768           // warp-tiles (x16 points)

#define PSTRIDE_B 400          // 25 x 16B per point (24 chunks used, odd stride)
#define AWARP_B   (16 * PSTRIDE_B)       // 6400 B
#define SMEM_TOTAL (4 * AWARP_B)         // 25600 B

__device__ uint2 g_B2[768];   // [sb(6)][r(4)][n(32)] -> (b0, b1)
__device__ float g_M;

// ---------------- helpers ----------------
__device__ __forceinline__ u32 smem_u32(const void* p) {
    u32 a; asm("{ .reg .u64 t; cvta.to.shared.u64 t, %1; cvt.u32.u64 %0, t; }"
               : "=r"(a) : "l"(p)); return a;
}
__device__ __forceinline__ float ex2f(float x) {
    float r; asm("ex2.approx.f32 %0, %1;" : "=f"(r) : "f"(x)); return r;
}
// pack bf16-truncations of (a, b): result = {hi16(b), hi16(a)}
__device__ __forceinline__ u32 prmt7632(float a, float b) {
    u32 r; asm("prmt.b32 %0, %1, %2, 0x7632;"
               : "=r"(r) : "r"(__float_as_uint(a)), "r"(__float_as_uint(b)));
    return r;
}
__device__ __forceinline__ void sts128(u32 addr, u32 a, u32 b, u32 c, u32 d) {
    asm volatile("st.shared.v4.b32 [%0], {%1, %2, %3, %4};"
                 :: "r"(addr), "r"(a), "r"(b), "r"(c), "r"(d) : "memory");
}
__device__ __forceinline__ void lds128(u32& a, u32& b, u32& c, u32& d, u32 addr) {
    asm volatile("ld.shared.v4.b32 {%0, %1, %2, %3}, [%4];"
                 : "=r"(a), "=r"(b), "=r"(c), "=r"(d) : "r"(addr));
}
__device__ __forceinline__ void mma_bf16(float& d0, float& d1, float& d2, float& d3,
                                         u32 a0, u32 a1, u32 a2, u32 a3,
                                         u32 b0, u32 b1) {
    asm volatile(
        "mma.sync.aligned.m16n8k16.row.col.f32.bf16.bf16.f32 "
        "{%0,%1,%2,%3}, {%4,%5,%6,%7}, {%8,%9}, {%0,%1,%2,%3};"
        : "+f"(d0), "+f"(d1), "+f"(d2), "+f"(d3)
        : "r"(a0), "r"(a1), "r"(a2), "r"(a3), "r"(b0), "r"(b1));
}

__device__ __forceinline__ int tri(int i, int j) { return i * (i + 1) / 2 + j; }

// fill 48 padded features of one point
__device__ __forceinline__ void features(const float xx[8], float v[48]) {
    int idx = 0;
#pragma unroll
    for (int i = 0; i < 8; i++)
#pragma unroll
        for (int j = i; j < 8; j++)
            v[idx++] = xx[i] * xx[j];
#pragma unroll
    for (int i = 0; i < 8; i++) v[36 + i] = xx[i];
    v[44] = 1.0f; v[45] = 0.0f; v[46] = 0.0f; v[47] = 0.0f;
}

// Staging. Pair index p packs features (2p, 2p+1). k-pair j in [0,96):
//   j 0..23 -> hi[j], 24..47 -> hi[j-24], 48..71 -> lo[j-48], 72..95 -> lo[j-72].
// Chunk ci = c*4+rv (16B) = {W[16c+rv], W[16c+rv+4], W[16c+rv+8], W[16c+rv+12]}.
// ph0 stages c 0..2 (hi region), ph1 stages c 3..5 (lo region).
template<int PH>
__device__ __forceinline__ void stageA(const float xx[8], u32 arow) {
    float v[48];
    features(xx, v);
    if (PH == 0) {
        u32 hi[24];
#pragma unroll
        for (int p = 0; p < 24; p++) hi[p] = prmt7632(v[2 * p], v[2 * p + 1]);
#pragma unroll
        for (int rv = 0; rv < 4; rv++) {
            sts128(arow + (0 * 4 + rv) * 16, hi[rv], hi[rv + 4], hi[rv + 8], hi[rv + 12]);
            sts128(arow + (1 * 4 + rv) * 16, hi[rv + 16], hi[rv + 20], hi[rv], hi[rv + 4]);
            sts128(arow + (2 * 4 + rv) * 16, hi[rv + 8], hi[rv + 12], hi[rv + 16], hi[rv + 20]);
        }
    } else {
        u32 lo[24];
#pragma unroll
        for (int p = 0; p < 24; p++) {
            float f0 = v[2 * p], f1 = v[2 * p + 1];
            float l0 = f0 - __uint_as_float(__float_as_uint(f0) & 0xFFFF0000u);
            float l1 = f1 - __uint_as_float(__float_as_uint(f1) & 0xFFFF0000u);
            lo[p] = prmt7632(l0, l1);
        }
#pragma unroll
        for (int rv = 0; rv < 4; rv++) {
            sts128(arow + (3 * 4 + rv) * 16, lo[rv], lo[rv + 4], lo[rv + 8], lo[rv + 12]);
            sts128(arow + (4 * 4 + rv) * 16, lo[rv + 16], lo[rv + 20], lo[rv], lo[rv + 4]);
            sts128(arow + (5 * 4 + rv) * 16, lo[rv + 8], lo[rv + 12], lo[rv + 16], lo[rv + 20]);
        }
    }
}

// ---------------- prep: 32 threads, one per component ----------------
__global__ void gmm_prep(const float* __restrict__ pi,
                         const float* __restrict__ means,
                         const float* __restrict__ cv) {
    const int k = threadIdx.x;

    float L[36];
#pragma unroll
    for (int i = 0; i < 8; i++)
#pragma unroll
        for (int j = 0; j <= i; j++)
            L[tri(i, j)] = cv[k * 64 + i * 8 + j];

    float Ld[8];
#pragma unroll
    for (int i = 0; i < 8; i++) Ld[i] = __fdividef(1.0f, L[tri(i, i)]);

    float W[36];
#pragma unroll
    for (int c = 0; c < 8; c++) {
        W[tri(c, c)] = Ld[c];
#pragma unroll
        for (int i = c + 1; i < 8; i++) {
            float t = 0.0f;
#pragma unroll
            for (int p = c; p < i; p++) t += L[tri(i, p)] * W[tri(p, c)];
            W[tri(i, c)] = -t * Ld[i];
        }
    }

    float Pm[8][8];
#pragma unroll
    for (int i = 0; i < 8; i++)
#pragma unroll
        for (int j = i; j < 8; j++) {
            float s = 0.0f;
#pragma unroll
            for (int m = j; m < 8; m++) s += W[tri(m, i)] * W[tri(m, j)];
            Pm[i][j] = s; Pm[j][i] = s;
        }

    float mu[8], h[8];
#pragma unroll
    for (int j = 0; j < 8; j++) mu[j] = means[k * 8 + j];
    float q0 = 0.0f;
#pragma unroll
    for (int i = 0; i < 8; i++) {
        float t = 0.0f;
#pragma unroll
        for (int j = 0; j < 8; j++) t += Pm[i][j] * mu[j];
        h[i] = t; q0 += mu[i] * t;
    }

    float logdet = 0.0f;
#pragma unroll
    for (int i = 0; i < 8; i++) logdet += __logf(fabsf(L[tri(i, i)]));
    logdet *= 2.0f;

    float pk = pi[k];
    float mx = pk;
#pragma unroll
    for (int o = 16; o; o >>= 1) mx = fmaxf(mx, __shfl_xor_sync(0xffffffffu, mx, o));
    float se = __expf(pk - mx);
#pragma unroll
    for (int o = 16; o; o >>= 1) se += __shfl_xor_sync(0xffffffffu, se, o);
    float lp = pk - mx - __logf(se);

    const float LOG2E = 1.4426950408889634f;
    const float LOG_2PI = 1.8378770664093453f;
    const float s2 = 0.5f * LOG2E;
    float cst2 = (lp - 0.5f * (8.0f * LOG_2PI + logdet)) * LOG2E;

    float M2 = cst2;
#pragma unroll
    for (int o = 16; o; o >>= 1) M2 = fmaxf(M2, __shfl_xor_sync(0xffffffffu, M2, o));

    float Cc[48];
    int idx = 0;
#pragma unroll
    for (int i = 0; i < 8; i++)
#pragma unroll
        for (int j = i; j < 8; j++)
            Cc[idx++] = (i == j) ? -s2 * Pm[i][i] : -2.0f * s2 * Pm[i][j];
#pragma unroll
    for (int i = 0; i < 8; i++) Cc[36 + i] = 2.0f * s2 * h[i];
    Cc[44] = cst2 - M2 - s2 * q0;
    Cc[45] = 0.0f; Cc[46] = 0.0f; Cc[47] = 0.0f;

    // 2-term bf16 split of coefs
    u16 c1b[48], c2b[48];
#pragma unroll
    for (int c = 0; c < 48; c++) {
        __nv_bfloat16 b1 = __float2bfloat16(Cc[c]);
        float f1 = __bfloat162float(b1);
        __nv_bfloat16 b2 = __float2bfloat16(Cc[c] - f1);
        c1b[c] = __bfloat16_as_ushort(b1);
        c2b[c] = __bfloat16_as_ushort(b2);
    }

    // B fragments: steps sb 0..5 (0-2 = C1, 3-5 = C2), thread-in-group r:
    // b0 = features (16*sib+2r, +1), b1 = (+8, +9), col n = k
    for (int sb = 0; sb < 6; sb++) {
        const int sib = sb % 3;
        const u16* S = (sb < 3) ? c1b : c2b;
        for (int r = 0; r < 4; r++) {
            int fb = 16 * sib + 2 * r;
            u32 b0 = (u32)S[fb]     | ((u32)S[fb + 1] << 16);
            u32 b1 = (u32)S[fb + 8] | ((u32)S[fb + 9] << 16);
            g_B2[sb * 128 + r * 32 + k] = make_uint2(b0, b1);
        }
    }
    if (k == 0) g_M = M2 * 0.69314718055994531f;
}

// ---------------- main: persistent, B in registers ----------------
__global__ void __launch_bounds__(TPB, 4)
gmm_main(const float* __restrict__ x, float* __restrict__ out) {
    extern __shared__ __align__(16) char smem[];
    const int tid = threadIdx.x;
    const int wid = tid >> 5;
    const int lane = tid & 31;
    const u32 sa = smem_u32(smem) + (u32)wid * AWARP_B;

    const int g = lane >> 2;      // mma row group 0..7
    const int r = lane & 3;       // thread-in-group 0..3
    const int pl = lane >> 1;     // staged point 0..15
    const int ph = lane & 1;      // staging half

    // B fragments: 6 steps x 4 n-tiles x (b0,b1) = 48 regs
    u32 bf[48];
#pragma unroll
    for (int sb = 0; sb < 6; sb++)
#pragma unroll
        for (int nt = 0; nt < 4; nt++) {
            uint2 v = g_B2[sb * 128 + r * 32 + nt * 8 + g];
            bf[(sb * 4 + nt) * 2]     = v.x;
            bf[(sb * 4 + nt) * 2 + 1] = v.y;
        }
    const float Mc = g_M;

    const u32 arow   = sa + (u32)pl * PSTRIDE_B;
    const u32 agrow0 = sa + (u32)g * PSTRIDE_B + (u32)r * 16;
    const u32 agrow1 = agrow0 + 8 * PSTRIDE_B;

    int tile = blockIdx.x * 4 + wid;

#pragma unroll 1
    while (tile < NW) {
        const int base = tile * 16;

        // ---- load x + stage A (2 lanes per point) ----
        {
            const float4* px = reinterpret_cast<const float4*>(x + (size_t)(base + pl) * 8);
            float4 a0 = px[0], a1 = px[1];
            float xx[8] = {a0.x, a0.y, a0.z, a0.w, a1.x, a1.y, a1.z, a1.w};
            if (ph == 0) stageA<0>(xx, arow);
            else         stageA<1>(xx, arow);
        }
        __syncwarp();

        // ---- 48 HMMA: per c, 2 LDS.128 then 8 mma (steps 2c, 2c+1) ----
        float d[4][4];
#pragma unroll
        for (int nt = 0; nt < 4; nt++)
#pragma unroll
            for (int e = 0; e < 4; e++) d[nt][e] = 0.0f;

#pragma unroll
        for (int c = 0; c < 6; c++) {
            u32 g0, g1, g2, g3, h0, h1, h2, h3;
            lds128(g0, g1, g2, g3, agrow0 + c * 64);   // row g:  steps 2c, 2c+1
            lds128(h0, h1, h2, h3, agrow1 + c * 64);   // row g+8
            const int sbe = (2 * c) % 6;
            const int sbo = (2 * c + 1) % 6;
#pragma unroll
            for (int nt = 0; nt < 4; nt++)
                mma_bf16(d[nt][0], d[nt][1], d[nt][2], d[nt][3],
                         g0, h0, g1, h1,
                         bf[(sbe * 4 + nt) * 2], bf[(sbe * 4 + nt) * 2 + 1]);
#pragma unroll
            for (int nt = 0; nt < 4; nt++)
                mma_bf16(d[nt][0], d[nt][1], d[nt][2], d[nt][3],
                         g2, h2, g3, h3,
                         bf[(sbo * 4 + nt) * 2], bf[(sbo * 4 + nt) * 2 + 1]);
        }
        __syncwarp();

        // ---- epilogue: thread (g,r) holds comps {nt*8+2r, +1} of points g, g+8 ----
        float s0 = 0.0f, s1 = 0.0f;
#pragma unroll
        for (int nt = 0; nt < 4; nt++) {
            s0 += ex2f(d[nt][0]) + ex2f(d[nt][1]);
            s1 += ex2f(d[nt][2]) + ex2f(d[nt][3]);
        }
        s0 += __shfl_xor_sync(0xffffffffu, s0, 1);
        s0 += __shfl_xor_sync(0xffffffffu, s0, 2);
        s1 += __shfl_xor_sync(0xffffffffu, s1, 1);
        s1 += __shfl_xor_sync(0xffffffffu, s1, 2);
        if (r == 0) {
            out[base + g]     = Mc + __logf(fmaxf(s0, 1e-37f));
            out[base + 8 + g] = Mc + __logf(fmaxf(s1, 1e-37f));
        }

        tile += TW;
    }
}

extern "C" void kernel_launch(void* const* d_in, const int* in_sizes, int n_in,
                              void* d_out, int out_size) {
    const float* x     = (const float*)d_in[0];
    const float* pi    = (const float*)d_in[1];
    const float* means = (const float*)d_in[2];
    const float* cv    = (const float*)d_in[3];
    float* out = (float*)d_out;

    gmm_prep<<<1, 32>>>(pi, means, cv);
    gmm_main<<<GRIDN, TPB, SMEM_TOTAL>>>(x, out);
}

// round 12
// speedup vs baseline: 2.1895x; 1.3743x over previous
#include <cuda_runtime.h>
#include <cuda_bf16.h>
#include <cstdint>

// GMM log-likelihood, N=524288, K=32, D=8 — bf16 mma.sync m16n8k16, round 12
// (round 11 with the feature-table bug fixed: linear features are x_i, not x_i*x_0).
//
// wll[n,k] = sum_c F[n][c]*C[k][c]; 48 padded features F = [x_i*x_j (i<=j),
// x_i, 1, pad]; coefs from precision matrix P = W^T W; log2 domain, max
// const folded. 3-term bf16 product over K=144:
//   A = [F1 F1 F2], B = [C1 C2 C1]   (F2*C2 dropped, ~2^-16 residual)
// F1 = bf16-truncation (PRMT pack), F2 = trunc(F - F1); C split by rn (prep).
//
// smem: F1 block stored ONCE (read twice, B differs). Per point 224 B:
//   [0..63]   hi LDS.128 chunks rv: (W[rv], W[rv+4], W[8+rv], W[12+rv])
//   [64..95]  hi LDS.64: (W[16+rv], W[20+rv])
//   [112..207] lo, same shape (odd chunk base -> STS parity-disjoint)
// Staging is branchless: part = f - as_float(bits(f) & (ph?0xFFFF0000:0)).
// Per warp-tile: 8 STS + 8 LDS + 36 HMMA. B fragments in 48 regs.

typedef unsigned int u32;
typedef unsigned short u16;

#define TPB    128
#define GRIDN  608             // 152 SMs x 4 CTAs
#define TW     (GRIDN * 4)     // 2432 warps
#define NW     32768           // warp-tiles (x16 points)

#define PSTRIDE_B 224          // 14 x 16B per point
#define AWARP_B   (16 * PSTRIDE_B)       // 3584 B
#define SMEM_TOTAL (4 * AWARP_B)         // 14336 B

__device__ uint2 g_B2[768];   // [q(6)][r(4)][n(32)] -> (b0, b1); q = cc*3+s
__device__ float g_M;

// ---------------- helpers ----------------
__device__ __forceinline__ u32 smem_u32(const void* p) {
    u32 a; asm("{ .reg .u64 t; cvta.to.shared.u64 t, %1; cvt.u32.u64 %0, t; }"
               : "=r"(a) : "l"(p)); return a;
}
__device__ __forceinline__ float ex2f(float x) {
    float r; asm("ex2.approx.f32 %0, %1;" : "=f"(r) : "f"(x)); return r;
}
// pack top16(a), top16(b) -> {hi16(b):hi16(a)}
__device__ __forceinline__ u32 prmt7632(float a, float b) {
    u32 r; asm("prmt.b32 %0, %1, %2, 0x7632;"
               : "=r"(r) : "r"(__float_as_uint(a)), "r"(__float_as_uint(b)));
    return r;
}
__device__ __forceinline__ void sts128(u32 addr, u32 a, u32 b, u32 c, u32 d) {
    asm volatile("st.shared.v4.b32 [%0], {%1, %2, %3, %4};"
                 :: "r"(addr), "r"(a), "r"(b), "r"(c), "r"(d) : "memory");
}
__device__ __forceinline__ void sts64(u32 addr, u32 a, u32 b) {
    asm volatile("st.shared.v2.b32 [%0], {%1, %2};" :: "r"(addr), "r"(a), "r"(b) : "memory");
}
__device__ __forceinline__ void lds128(u32& a, u32& b, u32& c, u32& d, u32 addr) {
    asm volatile("ld.shared.v4.b32 {%0, %1, %2, %3}, [%4];"
                 : "=r"(a), "=r"(b), "=r"(c), "=r"(d) : "r"(addr));
}
__device__ __forceinline__ void lds64(u32& a, u32& b, u32 addr) {
    asm volatile("ld.shared.v2.b32 {%0, %1}, [%2];" : "=r"(a), "=r"(b) : "r"(addr));
}
__device__ __forceinline__ void mma_bf16(float& d0, float& d1, float& d2, float& d3,
                                         u32 a0, u32 a1, u32 a2, u32 a3,
                                         u32 b0, u32 b1) {
    asm volatile(
        "mma.sync.aligned.m16n8k16.row.col.f32.bf16.bf16.f32 "
        "{%0,%1,%2,%3}, {%4,%5,%6,%7}, {%8,%9}, {%0,%1,%2,%3};"
        : "+f"(d0), "+f"(d1), "+f"(d2), "+f"(d3)
        : "r"(a0), "r"(a1), "r"(a2), "r"(a3), "r"(b0), "r"(b1));
}

__device__ __forceinline__ int tri(int i, int j) { return i * (i + 1) / 2 + j; }

// feature c of a point — c is a compile-time literal under full unroll, so
// this branch chain folds. (Round-11 regression: table form mapped the
// linear features to x_i*x_0. Keep the explicit branches.)
__device__ __forceinline__ float fv(const float xx[8], int c) {
    const int FI_[36] = {0,0,0,0,0,0,0,0, 1,1,1,1,1,1,1, 2,2,2,2,2,2,
                         3,3,3,3,3, 4,4,4,4, 5,5,5, 6,6, 7};
    const int FJ_[36] = {0,1,2,3,4,5,6,7, 1,2,3,4,5,6,7, 2,3,4,5,6,7,
                         3,4,5,6,7, 4,5,6,7, 5,6,7, 6,7, 7};
    if (c >= 45) return 0.0f;
    if (c == 44) return 1.0f;
    if (c >= 36) return xx[c - 36];
    return xx[FI_[c]] * xx[FJ_[c]];
}

// ---------------- prep: 32 threads, one per component ----------------
__global__ void gmm_prep(const float* __restrict__ pi,
                         const float* __restrict__ means,
                         const float* __restrict__ cv) {
    const int k = threadIdx.x;

    float L[36];
#pragma unroll
    for (int i = 0; i < 8; i++)
#pragma unroll
        for (int j = 0; j <= i; j++)
            L[tri(i, j)] = cv[k * 64 + i * 8 + j];

    float Ld[8];
#pragma unroll
    for (int i = 0; i < 8; i++) Ld[i] = __fdividef(1.0f, L[tri(i, i)]);

    float W[36];
#pragma unroll
    for (int c = 0; c < 8; c++) {
        W[tri(c, c)] = Ld[c];
#pragma unroll
        for (int i = c + 1; i < 8; i++) {
            float t = 0.0f;
#pragma unroll
            for (int p = c; p < i; p++) t += L[tri(i, p)] * W[tri(p, c)];
            W[tri(i, c)] = -t * Ld[i];
        }
    }

    float Pm[8][8];
#pragma unroll
    for (int i = 0; i < 8; i++)
#pragma unroll
        for (int j = i; j < 8; j++) {
            float s = 0.0f;
#pragma unroll
            for (int m = j; m < 8; m++) s += W[tri(m, i)] * W[tri(m, j)];
            Pm[i][j] = s; Pm[j][i] = s;
        }

    float mu[8], h[8];
#pragma unroll
    for (int j = 0; j < 8; j++) mu[j] = means[k * 8 + j];
    float q0 = 0.0f;
#pragma unroll
    for (int i = 0; i < 8; i++) {
        float t = 0.0f;
#pragma unroll
        for (int j = 0; j < 8; j++) t += Pm[i][j] * mu[j];
        h[i] = t; q0 += mu[i] * t;
    }

    float logdet = 0.0f;
#pragma unroll
    for (int i = 0; i < 8; i++) logdet += __logf(fabsf(L[tri(i, i)]));
    logdet *= 2.0f;

    float pk = pi[k];
    float mx = pk;
#pragma unroll
    for (int o = 16; o; o >>= 1) mx = fmaxf(mx, __shfl_xor_sync(0xffffffffu, mx, o));
    float se = __expf(pk - mx);
#pragma unroll
    for (int o = 16; o; o >>= 1) se += __shfl_xor_sync(0xffffffffu, se, o);
    float lp = pk - mx - __logf(se);

    const float LOG2E = 1.4426950408889634f;
    const float LOG_2PI = 1.8378770664093453f;
    const float s2 = 0.5f * LOG2E;
    float cst2 = (lp - 0.5f * (8.0f * LOG_2PI + logdet)) * LOG2E;

    float M2 = cst2;
#pragma unroll
    for (int o = 16; o; o >>= 1) M2 = fmaxf(M2, __shfl_xor_sync(0xffffffffu, M2, o));

    float Cc[48];
    int idx = 0;
#pragma unroll
    for (int i = 0; i < 8; i++)
#pragma unroll
        for (int j = i; j < 8; j++)
            Cc[idx++] = (i == j) ? -s2 * Pm[i][i] : -2.0f * s2 * Pm[i][j];
#pragma unroll
    for (int i = 0; i < 8; i++) Cc[36 + i] = 2.0f * s2 * h[i];
    Cc[44] = cst2 - M2 - s2 * q0;
    Cc[45] = 0.0f; Cc[46] = 0.0f; Cc[47] = 0.0f;

    u16 c1b[48], c2b[48];
#pragma unroll
    for (int c = 0; c < 48; c++) {
        __nv_bfloat16 b1 = __float2bfloat16(Cc[c]);
        float f1 = __bfloat162float(b1);
        __nv_bfloat16 b2 = __float2bfloat16(Cc[c] - f1);
        c1b[c] = __bfloat16_as_ushort(b1);
        c2b[c] = __bfloat16_as_ushort(b2);
    }

    // B fragments: q = cc*3 + s (cc 0 = C1, 1 = C2); step s covers feats 16s..16s+15
    for (int cc = 0; cc < 2; cc++) {
        const u16* S = cc ? c2b : c1b;
        for (int s = 0; s < 3; s++) {
            for (int r = 0; r < 4; r++) {
                int fb = 16 * s + 2 * r;
                u32 b0 = (u32)S[fb]     | ((u32)S[fb + 1] << 16);
                u32 b1 = (u32)S[fb + 8] | ((u32)S[fb + 9] << 16);
                g_B2[(cc * 3 + s) * 128 + r * 32 + k] = make_uint2(b0, b1);
            }
        }
    }
    if (k == 0) g_M = M2 * 0.69314718055994531f;
}

// ---------------- main: persistent, B in registers ----------------
__global__ void __launch_bounds__(TPB, 4)
gmm_main(const float* __restrict__ x, float* __restrict__ out) {
    extern __shared__ __align__(16) char smem[];
    const int tid = threadIdx.x;
    const int wid = tid >> 5;
    const int lane = tid & 31;
    const u32 sa = smem_u32(smem) + (u32)wid * AWARP_B;

    const int g = lane >> 2;      // mma row group 0..7
    const int r = lane & 3;       // thread-in-group 0..3
    const int pl = lane >> 1;     // staged point 0..15
    const int ph = lane & 1;      // staging half (0=hi, 1=lo)

    // B fragments: 6 q-steps x 4 n-tiles x (b0,b1) = 48 regs
    u32 bf[48];
#pragma unroll
    for (int q = 0; q < 6; q++)
#pragma unroll
        for (int nt = 0; nt < 4; nt++) {
            uint2 v = g_B2[q * 128 + r * 32 + nt * 8 + g];
            bf[(q * 4 + nt) * 2]     = v.x;
            bf[(q * 4 + nt) * 2 + 1] = v.y;
        }
    const float Mc = g_M;

    const u32 msk   = ph ? 0xFFFF0000u : 0u;
    const u32 abase = sa + (u32)pl * PSTRIDE_B + (ph ? 112u : 0u);
    const u32 ag0   = sa + (u32)g * PSTRIDE_B + (u32)r * 16;       // hi 128 row g
    const u32 ag1   = ag0 + 8 * PSTRIDE_B;                          // row g+8
    const u32 ag0q  = sa + (u32)g * PSTRIDE_B + 64 + (u32)r * 8;   // hi 64 row g
    const u32 ag1q  = ag0q + 8 * PSTRIDE_B;

    int tile = blockIdx.x * 4 + wid;

    float4 v0, v1;
    {
        const float4* px = reinterpret_cast<const float4*>(x + (size_t)(tile * 16 + pl) * 8);
        v0 = px[0]; v1 = px[1];
    }

#pragma unroll 1
    while (tile < NW) {
        const int base = tile * 16;
        const int tn = tile + TW;
        float xx[8] = {v0.x, v0.y, v0.z, v0.w, v1.x, v1.y, v1.z, v1.w};

        // ---- branchless staging: W[p] = pack(top16(f2p - sel), top16(f2p1 - sel)) ----
        {
            u32 Wp[24];
#pragma unroll
            for (int p = 0; p < 24; p++) {
                float f0 = fv(xx, 2 * p), f1 = fv(xx, 2 * p + 1);
                float t0 = __uint_as_float(__float_as_uint(f0) & msk);
                float t1 = __uint_as_float(__float_as_uint(f1) & msk);
                Wp[p] = prmt7632(f0 - t0, f1 - t1);
            }
#pragma unroll
            for (int rv = 0; rv < 4; rv++)
                sts128(abase + rv * 16, Wp[rv], Wp[rv + 4], Wp[8 + rv], Wp[12 + rv]);
#pragma unroll
            for (int rv = 0; rv < 4; rv++)
                sts64(abase + 64 + rv * 8, Wp[16 + rv], Wp[20 + rv]);
        }
        __syncwarp();

        // ---- prefetch next tile's x (hidden under MMA) ----
        if (tn < NW) {
            const float4* px = reinterpret_cast<const float4*>(x + (size_t)(tn * 16 + pl) * 8);
            v0 = px[0]; v1 = px[1];
        }

        // ---- A fragments: hi (u,va) and lo (w,z), rows g / g+8 ----
        u32 u0, u1, u2, u3, u4, u5, va0, va1, va2, va3, va4, va5;
        u32 w0, w1, w2, w3, w4, w5, z0, z1, z2, z3, z4, z5;
        lds128(u0, u1, u2, u3, ag0);
        lds128(va0, va1, va2, va3, ag1);
        lds64(u4, u5, ag0q);
        lds64(va4, va5, ag1q);
        lds128(w0, w1, w2, w3, ag0 + 112);
        lds128(z0, z1, z2, z3, ag1 + 112);
        lds64(w4, w5, ag0q + 112);
        lds64(z4, z5, ag1q + 112);

        float d[4][4];
#pragma unroll
        for (int nt = 0; nt < 4; nt++)
#pragma unroll
            for (int e = 0; e < 4; e++) d[nt][e] = 0.0f;

        // ---- 36 HMMA: steps s=0..2, each {hi x C1, hi x C2, lo x C1} x 4nt ----
#define MMA_STEP(A0, A1, A2, A3, Q)                                          \
        {                                                                     \
            _Pragma("unroll")                                                 \
            for (int nt = 0; nt < 4; nt++)                                    \
                mma_bf16(d[nt][0], d[nt][1], d[nt][2], d[nt][3],              \
                         A0, A1, A2, A3,                                      \
                         bf[((Q) * 4 + nt) * 2], bf[((Q) * 4 + nt) * 2 + 1]); \
        }
        MMA_STEP(u0, va0, u1, va1, 0)   // s0 hi x C1
        MMA_STEP(u0, va0, u1, va1, 3)   // s0 hi x C2
        MMA_STEP(w0, z0, w1, z1, 0)     // s0 lo x C1
        MMA_STEP(u2, va2, u3, va3, 1)   // s1 hi x C1
        MMA_STEP(u2, va2, u3, va3, 4)   // s1 hi x C2
        MMA_STEP(w2, z2, w3, z3, 1)     // s1 lo x C1
        MMA_STEP(u4, va4, u5, va5, 2)   // s2 hi x C1
        MMA_STEP(u4, va4, u5, va5, 5)   // s2 hi x C2
        MMA_STEP(w4, z4, w5, z5, 2)     // s2 lo x C1
#undef MMA_STEP

        // ---- epilogue: thread (g,r) holds comps {nt*8+2r, +1} of points g, g+8 ----
        float s0 = 0.0f, s1 = 0.0f;
#pragma unroll
        for (int nt = 0; nt < 4; nt++) {
            s0 += ex2f(d[nt][0]) + ex2f(d[nt][1]);
            s1 += ex2f(d[nt][2]) + ex2f(d[nt][3]);
        }
        s0 += __shfl_xor_sync(0xffffffffu, s0, 1);
        s0 += __shfl_xor_sync(0xffffffffu, s0, 2);
        s1 += __shfl_xor_sync(0xffffffffu, s1, 1);
        s1 += __shfl_xor_sync(0xffffffffu, s1, 2);
        if (r == 0) {
            out[base + g]     = Mc + __logf(fmaxf(s0, 1e-37f));
            out[base + 8 + g] = Mc + __logf(fmaxf(s1, 1e-37f));
        }

        __syncwarp();
        tile = tn;
    }
}

extern "C" void kernel_launch(void* const* d_in, const int* in_sizes, int n_in,
                              void* d_out, int out_size) {
    const float* x     = (const float*)d_in[0];
    const float* pi    = (const float*)d_in[1];
    const float* means = (const float*)d_in[2];
    const float* cv    = (const float*)d_in[3];
    float* out = (float*)d_out;

    gmm_prep<<<1, 32>>>(pi, means, cv);
    gmm_main<<<GRIDN, TPB, SMEM_TOTAL>>>(x, out);
}

// round 13
// speedup vs baseline: 2.3878x; 1.0906x over previous
#include <cuda_runtime.h>
#include <cuda_bf16.h>
#include <cstdint>

// GMM log-likelihood, N=524288, K=32, D=8 — bf16 mma.sync m16n8k16, round 13:
// one lane stages one full point; each warp iteration covers TWO m16 tiles
// (32 points) with independent accumulator chains (2x tensor ILP), and
// staging redundancy removed (round 12 had both lanes of a point computing
// all 48 features; hi lane also paid useless LOP+FADD).
//
// Math unchanged (round-12 verified): 48 padded features [x_i*x_j, x_i, 1],
// coefs from P = W^T W, log2 domain, max const folded; 3-term bf16 product
// A=[F1 F1 F2] x B=[C1 C2 C1] over K=144 (F2*C2 dropped, ~2^-16).
// smem byte layout per point (224 B) is IDENTICAL to round 12:
//   [0..63] hi 16B chunks rv: (W[rv],W[rv+4],W[8+rv],W[12+rv])
//   [64..95] hi pairs: 64+rv*8 = (W[16+rv],W[20+rv])   (written as 2 sts128)
//   [112..207] lo, same shape
// Per warp-iter: 12 STS.128 + 16 LDS + 72 HMMA. B fragments in 48 regs.

typedef unsigned int u32;
typedef unsigned short u16;

#define TPB    128
#define GRIDN  456             // 152 SMs x 3 CTAs
#define TW     (GRIDN * 4)     // 1824 warps
#define NI     16384           // warp-iterations (x32 points = 524288)

#define PSTRIDE_B 224          // 14 x 16B per point
#define AWARP_B   (32 * PSTRIDE_B)       // 7168 B (32 staged points)
#define SMEM_TOTAL (4 * AWARP_B)         // 28672 B

__device__ uint2 g_B2[768];   // [q(6)][r(4)][n(32)] -> (b0, b1); q = cc*3+s
__device__ float g_M;

// ---------------- helpers ----------------
__device__ __forceinline__ u32 smem_u32(const void* p) {
    u32 a; asm("{ .reg .u64 t; cvta.to.shared.u64 t, %1; cvt.u32.u64 %0, t; }"
               : "=r"(a) : "l"(p)); return a;
}
__device__ __forceinline__ float ex2f(float x) {
    float r; asm("ex2.approx.f32 %0, %1;" : "=f"(r) : "f"(x)); return r;
}
// pack top16(a), top16(b) -> {hi16(b):hi16(a)}
__device__ __forceinline__ u32 prmt7632(float a, float b) {
    u32 r; asm("prmt.b32 %0, %1, %2, 0x7632;"
               : "=r"(r) : "r"(__float_as_uint(a)), "r"(__float_as_uint(b)));
    return r;
}
__device__ __forceinline__ void sts128(u32 addr, u32 a, u32 b, u32 c, u32 d) {
    asm volatile("st.shared.v4.b32 [%0], {%1, %2, %3, %4};"
                 :: "r"(addr), "r"(a), "r"(b), "r"(c), "r"(d) : "memory");
}
__device__ __forceinline__ void lds128(u32& a, u32& b, u32& c, u32& d, u32 addr) {
    asm volatile("ld.shared.v4.b32 {%0, %1, %2, %3}, [%4];"
                 : "=r"(a), "=r"(b), "=r"(c), "=r"(d) : "r"(addr));
}
__device__ __forceinline__ void lds64(u32& a, u32& b, u32 addr) {
    asm volatile("ld.shared.v2.b32 {%0, %1}, [%2];" : "=r"(a), "=r"(b) : "r"(addr));
}
__device__ __forceinline__ void mma_bf16(float& d0, float& d1, float& d2, float& d3,
                                         u32 a0, u32 a1, u32 a2, u32 a3,
                                         u32 b0, u32 b1) {
    asm volatile(
        "mma.sync.aligned.m16n8k16.row.col.f32.bf16.bf16.f32 "
        "{%0,%1,%2,%3}, {%4,%5,%6,%7}, {%8,%9}, {%0,%1,%2,%3};"
        : "+f"(d0), "+f"(d1), "+f"(d2), "+f"(d3)
        : "r"(a0), "r"(a1), "r"(a2), "r"(a3), "r"(b0), "r"(b1));
}

__device__ __forceinline__ int tri(int i, int j) { return i * (i + 1) / 2 + j; }

// feature c — compile-time literal under full unroll (branch chain folds).
__device__ __forceinline__ float fv(const float xx[8], int c) {
    const int FI_[36] = {0,0,0,0,0,0,0,0, 1,1,1,1,1,1,1, 2,2,2,2,2,2,
                         3,3,3,3,3, 4,4,4,4, 5,5,5, 6,6, 7};
    const int FJ_[36] = {0,1,2,3,4,5,6,7, 1,2,3,4,5,6,7, 2,3,4,5,6,7,
                         3,4,5,6,7, 4,5,6,7, 5,6,7, 6,7, 7};
    if (c >= 45) return 0.0f;
    if (c == 44) return 1.0f;
    if (c >= 36) return xx[c - 36];
    return xx[FI_[c]] * xx[FJ_[c]];
}

// ---------------- prep: 32 threads, one per component (unchanged) ----------------
__global__ void gmm_prep(const float* __restrict__ pi,
                         const float* __restrict__ means,
                         const float* __restrict__ cv) {
    const int k = threadIdx.x;

    float L[36];
#pragma unroll
    for (int i = 0; i < 8; i++)
#pragma unroll
        for (int j = 0; j <= i; j++)
            L[tri(i, j)] = cv[k * 64 + i * 8 + j];

    float Ld[8];
#pragma unroll
    for (int i = 0; i < 8; i++) Ld[i] = __fdividef(1.0f, L[tri(i, i)]);

    float W[36];
#pragma unroll
    for (int c = 0; c < 8; c++) {
        W[tri(c, c)] = Ld[c];
#pragma unroll
        for (int i = c + 1; i < 8; i++) {
            float t = 0.0f;
#pragma unroll
            for (int p = c; p < i; p++) t += L[tri(i, p)] * W[tri(p, c)];
            W[tri(i, c)] = -t * Ld[i];
        }
    }

    float Pm[8][8];
#pragma unroll
    for (int i = 0; i < 8; i++)
#pragma unroll
        for (int j = i; j < 8; j++) {
            float s = 0.0f;
#pragma unroll
            for (int m = j; m < 8; m++) s += W[tri(m, i)] * W[tri(m, j)];
            Pm[i][j] = s; Pm[j][i] = s;
        }

    float mu[8], h[8];
#pragma unroll
    for (int j = 0; j < 8; j++) mu[j] = means[k * 8 + j];
    float q0 = 0.0f;
#pragma unroll
    for (int i = 0; i < 8; i++) {
        float t = 0.0f;
#pragma unroll
        for (int j = 0; j < 8; j++) t += Pm[i][j] * mu[j];
        h[i] = t; q0 += mu[i] * t;
    }

    float logdet = 0.0f;
#pragma unroll
    for (int i = 0; i < 8; i++) logdet += __logf(fabsf(L[tri(i, i)]));
    logdet *= 2.0f;

    float pk = pi[k];
    float mx = pk;
#pragma unroll
    for (int o = 16; o; o >>= 1) mx = fmaxf(mx, __shfl_xor_sync(0xffffffffu, mx, o));
    float se = __expf(pk - mx);
#pragma unroll
    for (int o = 16; o; o >>= 1) se += __shfl_xor_sync(0xffffffffu, se, o);
    float lp = pk - mx - __logf(se);

    const float LOG2E = 1.4426950408889634f;
    const float LOG_2PI = 1.8378770664093453f;
    const float s2 = 0.5f * LOG2E;
    float cst2 = (lp - 0.5f * (8.0f * LOG_2PI + logdet)) * LOG2E;

    float M2 = cst2;
#pragma unroll
    for (int o = 16; o; o >>= 1) M2 = fmaxf(M2, __shfl_xor_sync(0xffffffffu, M2, o));

    float Cc[48];
    int idx = 0;
#pragma unroll
    for (int i = 0; i < 8; i++)
#pragma unroll
        for (int j = i; j < 8; j++)
            Cc[idx++] = (i == j) ? -s2 * Pm[i][i] : -2.0f * s2 * Pm[i][j];
#pragma unroll
    for (int i = 0; i < 8; i++) Cc[36 + i] = 2.0f * s2 * h[i];
    Cc[44] = cst2 - M2 - s2 * q0;
    Cc[45] = 0.0f; Cc[46] = 0.0f; Cc[47] = 0.0f;

    u16 c1b[48], c2b[48];
#pragma unroll
    for (int c = 0; c < 48; c++) {
        __nv_bfloat16 b1 = __float2bfloat16(Cc[c]);
        float f1 = __bfloat162float(b1);
        __nv_bfloat16 b2 = __float2bfloat16(Cc[c] - f1);
        c1b[c] = __bfloat16_as_ushort(b1);
        c2b[c] = __bfloat16_as_ushort(b2);
    }

    // B fragments: q = cc*3 + s (cc 0 = C1, 1 = C2); step s covers feats 16s..16s+15
    for (int cc = 0; cc < 2; cc++) {
        const u16* S = cc ? c2b : c1b;
        for (int s = 0; s < 3; s++) {
            for (int r = 0; r < 4; r++) {
                int fb = 16 * s + 2 * r;
                u32 b0 = (u32)S[fb]     | ((u32)S[fb + 1] << 16);
                u32 b1 = (u32)S[fb + 8] | ((u32)S[fb + 9] << 16);
                g_B2[(cc * 3 + s) * 128 + r * 32 + k] = make_uint2(b0, b1);
            }
        }
    }
    if (k == 0) g_M = M2 * 0.69314718055994531f;
}

// ---------------- main: persistent, 2 m-tiles per warp iteration ----------------
__global__ void __launch_bounds__(TPB, 3)
gmm_main(const float* __restrict__ x, float* __restrict__ out) {
    extern __shared__ __align__(16) char smem[];
    const int tid = threadIdx.x;
    const int wid = tid >> 5;
    const int lane = tid & 31;
    const u32 sa = smem_u32(smem) + (u32)wid * AWARP_B;

    const int g = lane >> 2;      // mma row group 0..7
    const int r = lane & 3;       // thread-in-group 0..3

    // B fragments: 6 q-steps x 4 n-tiles x (b0,b1) = 48 regs
    u32 bf[48];
#pragma unroll
    for (int q = 0; q < 6; q++)
#pragma unroll
        for (int nt = 0; nt < 4; nt++) {
            uint2 v = g_B2[q * 128 + r * 32 + nt * 8 + g];
            bf[(q * 4 + nt) * 2]     = v.x;
            bf[(q * 4 + nt) * 2 + 1] = v.y;
        }
    const float Mc = g_M;

    const u32 arow = sa + (u32)lane * PSTRIDE_B;    // this lane's staged point
    // MMA read addresses for tiles A (rows 0..15) and B (rows 16..31)
    const u32 aA0  = sa + (u32)g * PSTRIDE_B + (u32)r * 16;
    const u32 aA1  = aA0 + 8 * PSTRIDE_B;
    const u32 aA0q = sa + (u32)g * PSTRIDE_B + 64 + (u32)r * 8;
    const u32 aA1q = aA0q + 8 * PSTRIDE_B;
    const u32 aB0  = aA0 + 16 * PSTRIDE_B;
    const u32 aB1  = aA1 + 16 * PSTRIDE_B;
    const u32 aB0q = aA0q + 16 * PSTRIDE_B;
    const u32 aB1q = aA1q + 16 * PSTRIDE_B;

    int it = blockIdx.x * 4 + wid;

    float4 v0, v1;
    {
        const float4* px = reinterpret_cast<const float4*>(x + (size_t)(it * 32 + lane) * 8);
        v0 = px[0]; v1 = px[1];
    }

#pragma unroll 1
    while (it < NI) {
        const int base = it * 32;
        const int in = it + TW;
        float xx[8] = {v0.x, v0.y, v0.z, v0.w, v1.x, v1.y, v1.z, v1.w};

        // ---- stage one full point per lane ----
        {
            u32 H[24], Lo[24];
#pragma unroll
            for (int p = 0; p < 24; p++) {
                float f0 = fv(xx, 2 * p), f1 = fv(xx, 2 * p + 1);
                H[p] = prmt7632(f0, f1);                      // hi: direct truncation
                float l0 = f0 - __uint_as_float(__float_as_uint(f0) & 0xFFFF0000u);
                float l1 = f1 - __uint_as_float(__float_as_uint(f1) & 0xFFFF0000u);
                Lo[p] = prmt7632(l0, l1);
            }
#pragma unroll
            for (int rv = 0; rv < 4; rv++)
                sts128(arow + rv * 16, H[rv], H[rv + 4], H[8 + rv], H[12 + rv]);
            sts128(arow + 64, H[16], H[20], H[17], H[21]);
            sts128(arow + 80, H[18], H[22], H[19], H[23]);
#pragma unroll
            for (int rv = 0; rv < 4; rv++)
                sts128(arow + 112 + rv * 16, Lo[rv], Lo[rv + 4], Lo[8 + rv], Lo[12 + rv]);
            sts128(arow + 176, Lo[16], Lo[20], Lo[17], Lo[21]);
            sts128(arow + 192, Lo[18], Lo[22], Lo[19], Lo[23]);
        }
        __syncwarp();

        // ---- prefetch next iteration's x ----
        if (in < NI) {
            const float4* px = reinterpret_cast<const float4*>(x + (size_t)(in * 32 + lane) * 8);
            v0 = px[0]; v1 = px[1];
        }

        // ---- A fragments for both tiles ----
        u32 u0,u1,u2,u3,u4,u5, va0,va1,va2,va3,va4,va5;      // tile A hi
        u32 w0,w1,w2,w3,w4,w5, z0,z1,z2,z3,z4,z5;            // tile A lo
        lds128(u0, u1, u2, u3, aA0);
        lds128(va0, va1, va2, va3, aA1);
        lds64(u4, u5, aA0q);
        lds64(va4, va5, aA1q);
        lds128(w0, w1, w2, w3, aA0 + 112);
        lds128(z0, z1, z2, z3, aA1 + 112);
        lds64(w4, w5, aA0q + 112);
        lds64(z4, z5, aA1q + 112);

        u32 m0,m1,m2,m3,m4,m5, n0,n1,n2,n3,n4,n5;            // tile B hi
        u32 o0,o1,o2,o3,o4,o5, q0,q1,q2,q3,q4,q5;            // tile B lo
        lds128(m0, m1, m2, m3, aB0);
        lds128(n0, n1, n2, n3, aB1);
        lds64(m4, m5, aB0q);
        lds64(n4, n5, aB1q);
        lds128(o0, o1, o2, o3, aB0 + 112);
        lds128(q0, q1, q2, q3, aB1 + 112);
        lds64(o4, o5, aB0q + 112);
        lds64(q4, q5, aB1q + 112);

        float dA[4][4], dB[4][4];
#pragma unroll
        for (int nt = 0; nt < 4; nt++)
#pragma unroll
            for (int e = 0; e < 4; e++) { dA[nt][e] = 0.0f; dB[nt][e] = 0.0f; }

#define MMA_STEP(D, A0, A1, A2, A3, Q)                                        \
        {                                                                     \
            _Pragma("unroll")                                                 \
            for (int nt = 0; nt < 4; nt++)                                    \
                mma_bf16(D[nt][0], D[nt][1], D[nt][2], D[nt][3],              \
                         A0, A1, A2, A3,                                      \
                         bf[((Q) * 4 + nt) * 2], bf[((Q) * 4 + nt) * 2 + 1]); \
        }
        // interleave the two tiles' chains for ILP
        MMA_STEP(dA, u0, va0, u1, va1, 0)
        MMA_STEP(dB, m0, n0, m1, n1, 0)
        MMA_STEP(dA, u0, va0, u1, va1, 3)
        MMA_STEP(dB, m0, n0, m1, n1, 3)
        MMA_STEP(dA, w0, z0, w1, z1, 0)
        MMA_STEP(dB, o0, q0, o1, q1, 0)
        MMA_STEP(dA, u2, va2, u3, va3, 1)
        MMA_STEP(dB, m2, n2, m3, n3, 1)
        MMA_STEP(dA, u2, va2, u3, va3, 4)
        MMA_STEP(dB, m2, n2, m3, n3, 4)
        MMA_STEP(dA, w2, z2, w3, z3, 1)
        MMA_STEP(dB, o2, q2, o3, q3, 1)
        MMA_STEP(dA, u4, va4, u5, va5, 2)
        MMA_STEP(dB, m4, n4, m5, n5, 2)
        MMA_STEP(dA, u4, va4, u5, va5, 5)
        MMA_STEP(dB, m4, n4, m5, n5, 5)
        MMA_STEP(dA, w4, z4, w5, z5, 2)
        MMA_STEP(dB, o4, q4, o5, q5, 2)
#undef MMA_STEP

        // ---- epilogue: 4 output points per thread-group ----
        float s0 = 0.0f, s1 = 0.0f, s2 = 0.0f, s3 = 0.0f;
#pragma unroll
        for (int nt = 0; nt < 4; nt++) {
            s0 += ex2f(dA[nt][0]) + ex2f(dA[nt][1]);
            s1 += ex2f(dA[nt][2]) + ex2f(dA[nt][3]);
            s2 += ex2f(dB[nt][0]) + ex2f(dB[nt][1]);
            s3 += ex2f(dB[nt][2]) + ex2f(dB[nt][3]);
        }
        s0 += __shfl_xor_sync(0xffffffffu, s0, 1);
        s0 += __shfl_xor_sync(0xffffffffu, s0, 2);
        s1 += __shfl_xor_sync(0xffffffffu, s1, 1);
        s1 += __shfl_xor_sync(0xffffffffu, s1, 2);
        s2 += __shfl_xor_sync(0xffffffffu, s2, 1);
        s2 += __shfl_xor_sync(0xffffffffu, s2, 2);
        s3 += __shfl_xor_sync(0xffffffffu, s3, 1);
        s3 += __shfl_xor_sync(0xffffffffu, s3, 2);
        if (r == 0) {
            out[base + g]      = Mc + __logf(fmaxf(s0, 1e-37f));
            out[base + 8 + g]  = Mc + __logf(fmaxf(s1, 1e-37f));
            out[base + 16 + g] = Mc + __logf(fmaxf(s2, 1e-37f));
            out[base + 24 + g] = Mc + __logf(fmaxf(s3, 1e-37f));
        }

        __syncwarp();
        it = in;
    }
}

extern "C" void kernel_launch(void* const* d_in, const int* in_sizes, int n_in,
                              void* d_out, int out_size) {
    const float* x     = (const float*)d_in[0];
    const float* pi    = (const float*)d_in[1];
    const float* means = (const float*)d_in[2];
    const float* cv    = (const float*)d_in[3];
    float* out = (float*)d_out;

    gmm_prep<<<1, 32>>>(pi, means, cv);
    gmm_main<<<GRIDN, TPB, SMEM_TOTAL>>>(x, out);
}